// round 9
// baseline (speedup 1.0000x reference)
#include <cuda_runtime.h>
#include <math.h>

// ---------------------------------------------------------------------------
// VanishingNet full pipeline, fp32, NHWC. R7: FFMA2-packed conv, hoisted dgcn,
// warp-per-bin hough/sphere.
// ---------------------------------------------------------------------------

#define kB     2
#define kC     128
#define kNPIX  16384
#define kHTH   184
#define kHTW   180
#define kNBINS (kHTH * kHTW)   /* 33120 */
#define kSN    1984            /* per-batch node rows: 1024 + 768 + 192 */
#define kNR    (kB * kSN)      /* 3968 */
#define kEPS   1e-5f

// --------------------------- scratch (device globals) ----------------------
__device__ float g_xT [kB * kNPIX * kC];    // BN+ReLU image, [b][p][c]
__device__ float g_ht [kB * kNBINS * kC];   // Hough map, [b][bin][c]
__device__ float g_hc [kB * kNBINS * kC];   // conv out, [b][bin][c]
__device__ float g_sph[kNR * kC];           // sphere features [r][c]
__device__ float g_y  [kNR * 64];           // sconv pre-BN
__device__ float g_xa [kNR * 64];           // dgcn ping
__device__ float g_xb [kNR * 64];           // dgcn pong
__device__ float g_simg[2 * kC];            // image BN stats
__device__ float g_sht [2 * kC];            // ht BN stats (atomics)
__device__ float g_ssc [2 * 192];           // sconv BN stats (atomics)
__device__ float g_bce [12];                // {sum_pos,sum_neg,npos,nneg} x3

__device__ __forceinline__ float warpSum(float v) {
    #pragma unroll
    for (int o = 16; o > 0; o >>= 1) v += __shfl_down_sync(0xffffffffu, v, o);
    return v;
}
__device__ __forceinline__ unsigned long long pk2(float lo, float hi) {
    unsigned long long r;
    asm("mov.b64 %0, {%1, %2};" : "=l"(r) : "f"(lo), "f"(hi));
    return r;
}
__device__ __forceinline__ float2 upk2(unsigned long long v) {
    float x, y;
    asm("mov.b64 {%0, %1}, %2;" : "=f"(x), "=f"(y) : "l"(v));
    return make_float2(x, y);
}
__device__ __forceinline__ void ffma2(unsigned long long &acc, unsigned long long a,
                                      unsigned long long b) {
    asm("fma.rn.f32x2 %0, %1, %2, %0;" : "+l"(acc) : "l"(a), "l"(b));
}

// --------------------------- k0: zero accumulators --------------------------
__global__ void k_zero() {
    int t = threadIdx.x;
    if (t < 2 * kC) { g_sht[t] = 0.f; }
    if (t < 384)    { g_ssc[t] = 0.f; }
    if (t < 12)     { g_bce[t] = 0.f; }
}

// --------------------------- k1: image BN stats ------------------------------
__global__ __launch_bounds__(256) void k_img_stats(const float* __restrict__ img) {
    int c = blockIdx.x, t = threadIdx.x;
    float s = 0.f, s2 = 0.f;
    for (int b = 0; b < kB; b++) {
        const float* p = img + (size_t)(b * kC + c) * kNPIX;
        for (int i = t; i < kNPIX; i += 256) { float v = p[i]; s += v; s2 += v * v; }
    }
    __shared__ float rs[8], rs2[8];
    int lane = t & 31, w = t >> 5;
    s = warpSum(s); s2 = warpSum(s2);
    if (lane == 0) { rs[w] = s; rs2[w] = s2; }
    __syncthreads();
    if (t == 0) {
        float a = 0.f, a2 = 0.f;
        #pragma unroll
        for (int i = 0; i < 8; i++) { a += rs[i]; a2 += rs2[i]; }
        g_simg[c] = a; g_simg[kC + c] = a2;
    }
}

// ---------------- k2: BN + ReLU + transpose to pixel-major -------------------
__global__ void k_bnt(const float* __restrict__ img, const float* __restrict__ gam,
                      const float* __restrict__ bet) {
    __shared__ float tile[32][33];
    int p0 = blockIdx.x * 32, c0 = blockIdx.y * 32, b = blockIdx.z;
    int tx = threadIdx.x, ty = threadIdx.y;
    #pragma unroll
    for (int i = 0; i < 4; i++) {
        int c = c0 + ty * 4 + i;
        tile[ty * 4 + i][tx] = img[(size_t)(b * kC + c) * kNPIX + p0 + tx];
    }
    __syncthreads();
    int c = c0 + tx;
    float mean = g_simg[c] * (1.f / 32768.f);
    float var  = g_simg[kC + c] * (1.f / 32768.f) - mean * mean;
    float sc = gam[c] * rsqrtf(var + kEPS);
    float bi = bet[c] - mean * sc;
    #pragma unroll
    for (int i = 0; i < 4; i++) {
        int p = p0 + ty * 4 + i;
        float v = tile[tx][ty * 4 + i];
        g_xT[(size_t)(b * kNPIX + p) * kC + c] = fmaxf(sc * v + bi, 0.f);
    }
}

// --------------------------- k3: Hough voting (warp per bin) -----------------
__global__ __launch_bounds__(256) void k_hough(const int* __restrict__ hidx,
                                               const float* __restrict__ hw) {
    int gw = blockIdx.x * 8 + (threadIdx.x >> 5);   // 0 .. 66239
    int lane = threadIdx.x & 31;
    int b = gw / kNBINS, bin = gw - b * kNBINS;
    int   iv = 0; float wv = 0.f;
    if (lane < 8) { iv = hidx[bin * 8 + lane]; wv = hw[bin * 8 + lane]; }
    const float4* xb = (const float4*)(g_xT + (size_t)b * kNPIX * kC);
    float4 acc = make_float4(0.f, 0.f, 0.f, 0.f);
    #pragma unroll
    for (int k = 0; k < 8; k++) {
        int   ik = __shfl_sync(0xffffffffu, iv, k);
        float wk = __shfl_sync(0xffffffffu, wv, k);
        float4 v = xb[(size_t)ik * 32 + lane];
        acc.x += wk * v.x; acc.y += wk * v.y; acc.z += wk * v.z; acc.w += wk * v.w;
    }
    ((float4*)g_ht)[(size_t)(b * kNBINS + bin) * 32 + lane] = acc;
}

// --------------------------- k4: 3x3 conv, FFMA2 over cout pairs -------------
// Block: 64 px (one y row) x 128 cout. Thread: 4 px x 8 co. cin chunks of 32.
// smem: sInDup [kh][px 0..65][ci] as duplicated (v,v) u64; sW [ci][co] floats.
#define SIN_U64  (3 * 66 * 32)                 /* 6336 u64 = 50688 B */
#define SMEM_CONV (SIN_U64 * 8 + 32 * 128 * 4) /* 67072 B */
__global__ __launch_bounds__(256, 2) void k_conv(const float* __restrict__ Wc) {
    extern __shared__ __align__(16) char smem[];
    unsigned long long* sd = (unsigned long long*)smem;          // sInDup
    float* sW = (float*)(smem + SIN_U64 * 8);                    // 32x128
    const int t    = threadIdx.x;
    const int xc0  = blockIdx.x * 64;
    const int y    = blockIdx.y;
    const int b    = blockIdx.z;
    const int lane = t & 31;
    const int warp = t >> 5;
    const int pg   = warp * 2 + (lane >> 4);    // pixel phase 0..15
    const int co0  = (lane & 15) * 8;           // 8 couts per thread
    unsigned long long acc[4][4];
    #pragma unroll
    for (int m = 0; m < 4; m++)
        #pragma unroll
        for (int j = 0; j < 4; j++) acc[m][j] = 0ull;

    for (int cc = 0; cc < 128; cc += 32) {
        __syncthreads();   // previous chunk's readers done with sd
        for (int i = t; i < SIN_U64; i += 256) {
            int ci = i & 31; int r2 = i >> 5; int px = r2 % 66; int kh = r2 / 66;
            int gy = y + kh - 1, gx = xc0 + px - 1;
            float v = 0.f;
            if ((unsigned)gy < kHTH && (unsigned)gx < kHTW)
                v = g_ht[(size_t)(b * kNBINS + gy * kHTW + gx) * kC + cc + ci];
            sd[(kh * 66 + px) * 32 + ci] = pk2(v, v);
        }
        #pragma unroll 1
        for (int tap = 0; tap < 9; tap++) {
            __syncthreads();   // sd ready / previous sW consumed
            const float* wp = Wc + (size_t)(tap * kC + cc) * kC;
            for (int i = t; i < 4096; i += 256) sW[i] = wp[i];
            __syncthreads();
            const int kh = tap / 3, kw = tap - kh * 3;
            const unsigned long long* Abase = sd + (kh * 66 + pg + kw) * 32;
            #pragma unroll 4
            for (int ci = 0; ci < 32; ci++) {
                unsigned long long A0 = Abase[ci];
                unsigned long long A1 = Abase[512 + ci];
                unsigned long long A2 = Abase[1024 + ci];
                unsigned long long A3 = Abase[1536 + ci];
                const float* wr = sW + ci * 128 + co0;
                ulonglong2 b01 = *(const ulonglong2*)wr;
                ulonglong2 b23 = *(const ulonglong2*)(wr + 4);
                ffma2(acc[0][0], A0, b01.x); ffma2(acc[0][1], A0, b01.y);
                ffma2(acc[0][2], A0, b23.x); ffma2(acc[0][3], A0, b23.y);
                ffma2(acc[1][0], A1, b01.x); ffma2(acc[1][1], A1, b01.y);
                ffma2(acc[1][2], A1, b23.x); ffma2(acc[1][3], A1, b23.y);
                ffma2(acc[2][0], A2, b01.x); ffma2(acc[2][1], A2, b01.y);
                ffma2(acc[2][2], A2, b23.x); ffma2(acc[2][3], A2, b23.y);
                ffma2(acc[3][0], A3, b01.x); ffma2(acc[3][1], A3, b01.y);
                ffma2(acc[3][2], A3, b23.x); ffma2(acc[3][3], A3, b23.y);
            }
        }
    }
    #pragma unroll
    for (int m = 0; m < 4; m++) {
        int gx = xc0 + pg + 16 * m;
        if (gx < kHTW) {
            float* orow = &g_hc[(size_t)(b * kNBINS + y * kHTW + gx) * kC + co0];
            float2 p0 = upk2(acc[m][0]), p1 = upk2(acc[m][1]);
            float2 p2 = upk2(acc[m][2]), p3 = upk2(acc[m][3]);
            *(float4*)orow       = make_float4(p0.x, p0.y, p1.x, p1.y);
            *(float4*)(orow + 4) = make_float4(p2.x, p2.y, p3.x, p3.y);
        }
    }
}

// --------------------------- k5: ht BN stats ---------------------------------
__global__ __launch_bounds__(128) void k_htstats() {
    int t = threadIdx.x, blk = blockIdx.x;
    int r0 = blk * 130, r1 = min(r0 + 130, kB * kNBINS);
    float s = 0.f, s2 = 0.f;
    for (int r = r0; r < r1; r++) {
        float v = g_hc[(size_t)r * kC + t];
        s += v; s2 += v * v;
    }
    atomicAdd(&g_sht[t], s);
    atomicAdd(&g_sht[kC + t], s2);
}

// ---------------- k6: sphere gather (warp per node, fused ht BN+ReLU) --------
__global__ __launch_bounds__(256) void k_sphere(const float* __restrict__ gam,
                                                const float* __restrict__ bet,
                                                const int* __restrict__ sph_idx,
                                                const float* __restrict__ sph_w,
                                                const int* __restrict__ ind0,
                                                const int* __restrict__ ind1,
                                                const int* __restrict__ ind2) {
    int gw = blockIdx.x * 8 + (threadIdx.x >> 5);   // 0 .. kNR-1
    int lane = threadIdx.x & 31;
    int b = gw / kSN, s = gw - b * kSN;
    int sp;
    if (s < 1024)      sp = ind0[b * 1024 + s];
    else if (s < 1792) sp = ind1[b * 768 + (s - 1024)];
    else               sp = ind2[b * 192 + (s - 1792)];
    int   iv = 0; float wv = 0.f;
    if (lane < 16) { iv = sph_idx[sp * 16 + lane]; wv = sph_w[sp * 16 + lane]; }
    const float inv = 1.f / (float)(kB * kNBINS);
    float4 s1 = ((const float4*)g_sht)[lane];
    float4 s2 = ((const float4*)g_sht)[32 + lane];
    float4 g4 = ((const float4*)gam)[lane];
    float4 b4 = ((const float4*)bet)[lane];
    float4 sc4, bi4;
    {
        float m, v;
        m = s1.x * inv; v = s2.x * inv - m * m; sc4.x = g4.x * rsqrtf(v + kEPS); bi4.x = b4.x - m * sc4.x;
        m = s1.y * inv; v = s2.y * inv - m * m; sc4.y = g4.y * rsqrtf(v + kEPS); bi4.y = b4.y - m * sc4.y;
        m = s1.z * inv; v = s2.z * inv - m * m; sc4.z = g4.z * rsqrtf(v + kEPS); bi4.z = b4.z - m * sc4.z;
        m = s1.w * inv; v = s2.w * inv - m * m; sc4.w = g4.w * rsqrtf(v + kEPS); bi4.w = b4.w - m * sc4.w;
    }
    const float4* base = (const float4*)(g_hc + (size_t)b * kNBINS * kC);
    float4 acc = make_float4(0.f, 0.f, 0.f, 0.f);
    #pragma unroll
    for (int k = 0; k < 16; k++) {
        int   ik = __shfl_sync(0xffffffffu, iv, k);
        float wk = __shfl_sync(0xffffffffu, wv, k);
        float4 v = base[(size_t)ik * 32 + lane];
        acc.x += wk * fmaxf(sc4.x * v.x + bi4.x, 0.f);
        acc.y += wk * fmaxf(sc4.y * v.y + bi4.y, 0.f);
        acc.z += wk * fmaxf(sc4.z * v.z + bi4.z, 0.f);
        acc.w += wk * fmaxf(sc4.w * v.w + bi4.w, 0.f);
    }
    ((float4*)g_sph)[(size_t)(b * kSN + s) * 32 + lane] = acc;
}

// --------------------------- k7: sconv (1x1 conv) + stats --------------------
__global__ __launch_bounds__(128) void k_sconv(const float* __restrict__ w_sc,
                                               const float* __restrict__ b_sc) {
    __shared__ float sWt[128 * 64];   // [c][o]
    __shared__ float sRow[2][128];
    int bx = blockIdx.x;
    int b = bx / 31, u = bx % 31;
    int sc, rbase;
    if (u < 16)      { sc = 0; rbase = b * kSN + u * 64; }
    else if (u < 28) { sc = 1; rbase = b * kSN + 1024 + (u - 16) * 64; }
    else             { sc = 2; rbase = b * kSN + 1792 + (u - 28) * 64; }
    int t = threadIdx.x, o = t & 63, half = t >> 6;
    for (int i = t; i < 8192; i += 128) {
        int c = i >> 6, oo = i & 63;
        sWt[i] = w_sc[(size_t)(sc * 64 + oo) * 128 + c];
    }
    __syncthreads();
    float bo = b_sc[sc * 64 + o];
    float ls = 0.f, ls2 = 0.f;
    for (int r0 = 0; r0 < 64; r0 += 2) {
        __syncthreads();
        sRow[0][t] = g_sph[(size_t)(rbase + r0) * 128 + t];
        sRow[1][t] = g_sph[(size_t)(rbase + r0 + 1) * 128 + t];
        __syncthreads();
        const float* rp = sRow[half];
        float acc = bo;
        #pragma unroll 8
        for (int c = 0; c < 128; c++) acc += rp[c] * sWt[c * 64 + o];
        g_y[(size_t)(rbase + r0 + half) * 64 + o] = acc;
        ls += acc; ls2 += acc * acc;
    }
    atomicAdd(&g_ssc[sc * 64 + o], ls);
    atomicAdd(&g_ssc[192 + sc * 64 + o], ls2);
}

// --------------------------- k8: sconv BN + ReLU -----------------------------
__global__ void k_scbn(const float* __restrict__ gam, const float* __restrict__ bet) {
    int idx = blockIdx.x * blockDim.x + threadIdx.x;
    if (idx >= kNR * 64) return;
    int r = idx >> 6, o = idx & 63;
    int s = r % kSN;
    int sc = (s < 1024) ? 0 : (s < 1792 ? 1 : 2);
    float cnt = (sc == 0) ? 2048.f : (sc == 1 ? 1536.f : 384.f);
    float mean = g_ssc[sc * 64 + o] / cnt;
    float var  = g_ssc[192 + sc * 64 + o] / cnt - mean * mean;
    float scv = gam[sc * 64 + o] * rsqrtf(var + kEPS);
    float bi  = bet[sc * 64 + o] - mean * scv;
    g_xa[idx] = fmaxf(scv * g_y[idx] + bi, 0.f);
}

// --------------------------- k9: one EdgeConv layer (center hoisted) ---------
// h = relu(xc@(W1-W2) + b + xn@W2); u = xc@(W1-W2)+b computed once per node.
__global__ __launch_bounds__(256) void k_dgcn(const float* __restrict__ xin,
                                              float* __restrict__ xout,
                                              const float* __restrict__ W,
                                              const float* __restrict__ bias,
                                              const int* __restrict__ e0,
                                              const int* __restrict__ e1,
                                              const int* __restrict__ e2,
                                              int sc) {
    __shared__ __align__(16) float sWd[64 * 64];  // W1 - W2, [c][o]
    __shared__ __align__(16) float sW2[64 * 64];  // W2, [c][o]
    __shared__ __align__(16) float sx[4][64], sn[4][64];
    int t = threadIdx.x;
    for (int i = t; i < 4096; i += 256) {
        float w1 = W[i], w2 = W[4096 + i];
        sWd[i] = w1 - w2;
        sW2[i] = w2;
    }
    int g64 = t >> 6, o = t & 63;
    int m = blockIdx.x * 4 + g64;

    int r, rbase, ecBase, enBase;
    const int* E;
    if (sc == 0) {
        int b = m >> 10, j = m & 1023;
        rbase = b * kSN; r = rbase + j;
        E = e0; ecBase = b * 2 * 8192 + j * 8; enBase = ecBase + 8192;
    } else if (sc == 1) {
        int g = m >> 8, j = m & 255;
        int b = g / 3, v = g - 3 * b;
        rbase = b * kSN + 1024 + v * 256; r = rbase + j;
        E = e1; ecBase = g * 2 * 2048 + j * 8; enBase = ecBase + 2048;
    } else {
        int g = m >> 6, j = m & 63;
        int b = g / 3, v = g - 3 * b;
        rbase = b * kSN + 1792 + v * 64; r = rbase + j;
        E = e2; ecBase = g * 2 * 512 + j * 8; enBase = ecBase + 512;
    }
    // center feature (constant across k: edges are repeat(arange(n), k))
    int ci0 = E[ecBase];
    sx[g64][o] = xin[(size_t)(rbase + ci0) * 64 + o];
    __syncthreads();
    float u = bias[o];
    {
        const float* px = sx[g64];
        #pragma unroll
        for (int c4 = 0; c4 < 16; c4++) {
            float4 a = *reinterpret_cast<const float4*>(&px[c4 * 4]);
            int cb = c4 * 4;
            u += a.x * sWd[(cb + 0) * 64 + o] + a.y * sWd[(cb + 1) * 64 + o]
               + a.z * sWd[(cb + 2) * 64 + o] + a.w * sWd[(cb + 3) * 64 + o];
        }
    }
    float mv = 0.f;   // relu output is >= 0
    #pragma unroll 1
    for (int kk = 0; kk < 8; kk++) {
        int ni = E[enBase + kk];
        __syncthreads();
        sn[g64][o] = xin[(size_t)(rbase + ni) * 64 + o];
        __syncthreads();
        float acc = u;
        const float* pn = sn[g64];
        #pragma unroll
        for (int c4 = 0; c4 < 16; c4++) {
            float4 n = *reinterpret_cast<const float4*>(&pn[c4 * 4]);
            int cb = c4 * 4;
            acc += n.x * sW2[(cb + 0) * 64 + o] + n.y * sW2[(cb + 1) * 64 + o]
                 + n.z * sW2[(cb + 2) * 64 + o] + n.w * sW2[(cb + 3) * 64 + o];
        }
        mv = fmaxf(mv, acc);
    }
    xout[(size_t)r * 64 + o] = mv;
}

// --------------------------- k10: head + BCE accumulation --------------------
__global__ __launch_bounds__(256) void k_head(const float* __restrict__ hw,
                                              const float* __restrict__ hb,
                                              const int* __restrict__ t0,
                                              const int* __restrict__ t1,
                                              const int* __restrict__ t2,
                                              float* __restrict__ out) {
    int t = threadIdx.x;
    int warp = t >> 5, lane = t & 31;
    int r = blockIdx.x * 8 + warp;
    if (r >= kNR) return;
    int b = r / kSN, s = r - b * kSN;
    int sc, tgt;
    if (s < 1024)      { sc = 0; tgt = t0[b * 1024 + s]; }
    else if (s < 1792) { sc = 1; int q = s - 1024; tgt = t1[(b * 3 + (q >> 8)) * 256 + (q & 255)]; }
    else               { sc = 2; int q = s - 1792; tgt = t2[(b * 3 + (q >> 6)) * 64 + (q & 63)]; }
    const float* x = g_xa + (size_t)r * 64;
    float partial = x[lane] * hw[sc * 64 + lane] + x[lane + 32] * hw[sc * 64 + lane + 32];
    partial = warpSum(partial);
    if (lane == 0) {
        float z = partial + hb[sc];
        out[6 + r] = 1.f / (1.f + expf(-z));
        float l = fmaxf(z, 0.f) - z * (float)tgt + log1pf(expf(-fabsf(z)));
        if (tgt > 0) { atomicAdd(&g_bce[sc * 4 + 0], l); atomicAdd(&g_bce[sc * 4 + 2], 1.f); }
        else         { atomicAdd(&g_bce[sc * 4 + 1], l); atomicAdd(&g_bce[sc * 4 + 3], 1.f); }
    }
}

// --------------------------- k11: finalize losses ----------------------------
__global__ void k_final(float* __restrict__ out) {
    int sc = threadIdx.x;
    if (sc < 3) {
        float np = fmaxf(g_bce[sc * 4 + 2], 1.f);
        float nn = fmaxf(g_bce[sc * 4 + 3], 1.f);
        out[sc * 2 + 0] = g_bce[sc * 4 + 0] / np;
        out[sc * 2 + 1] = g_bce[sc * 4 + 1] / nn;
    }
}

// ---------------------------------------------------------------------------
extern "C" void kernel_launch(void* const* d_in, const int* in_sizes, int n_in,
                              void* d_out, int out_size) {
    const float* image      = (const float*)d_in[0];
    const float* bn_gamma   = (const float*)d_in[1];
    const float* bn_beta    = (const float*)d_in[2];
    const int*   ht_idx     = (const int*)  d_in[3];
    const float* ht_w       = (const float*)d_in[4];
    const float* w_htconv   = (const float*)d_in[5];
    const float* htbn_gamma = (const float*)d_in[6];
    const float* htbn_beta  = (const float*)d_in[7];
    const int*   sph_idx    = (const int*)  d_in[8];
    const float* sph_w      = (const float*)d_in[9];
    const float* w_sc       = (const float*)d_in[10];
    const float* b_sc       = (const float*)d_in[11];
    const float* scbn_gamma = (const float*)d_in[12];
    const float* scbn_beta  = (const float*)d_in[13];
    const float* dgcn_w     = (const float*)d_in[14];
    const float* dgcn_b     = (const float*)d_in[15];
    const float* dgcn_hw    = (const float*)d_in[16];
    const float* dgcn_hb    = (const float*)d_in[17];
    const int*   ind0       = (const int*)  d_in[18];
    const int*   ind1       = (const int*)  d_in[19];
    const int*   ind2       = (const int*)  d_in[20];
    const int*   edge0      = (const int*)  d_in[21];
    const int*   edge1      = (const int*)  d_in[22];
    const int*   edge2      = (const int*)  d_in[23];
    const int*   target0    = (const int*)  d_in[24];
    const int*   target1    = (const int*)  d_in[25];
    const int*   target2    = (const int*)  d_in[26];
    float* out = (float*)d_out;

    static bool attr_done = false;
    if (!attr_done) {
        cudaFuncSetAttribute(k_conv, cudaFuncAttributeMaxDynamicSharedMemorySize,
                             SMEM_CONV);
        attr_done = true;
    }

    k_zero<<<1, 512>>>();
    k_img_stats<<<kC, 256>>>(image);
    k_bnt<<<dim3(kNPIX / 32, kC / 32, kB), dim3(32, 8)>>>(image, bn_gamma, bn_beta);
    k_hough<<<(kB * kNBINS) / 8, 256>>>(ht_idx, ht_w);
    k_conv<<<dim3(3, kHTH, kB), 256, SMEM_CONV>>>(w_htconv);
    k_htstats<<<510, 128>>>();
    k_sphere<<<kNR / 8, 256>>>(htbn_gamma, htbn_beta, sph_idx, sph_w,
                               ind0, ind1, ind2);
    k_sconv<<<62, 128>>>(w_sc, b_sc);
    k_scbn<<<(kNR * 64 + 255) / 256, 256>>>(scbn_gamma, scbn_beta);

    // dgcn: 4 layers x 3 scales; ping-pong g_xa <-> g_xb
    float* xa; float* xb;
    cudaGetSymbolAddress((void**)&xa, g_xa);
    cudaGetSymbolAddress((void**)&xb, g_xb);
    const int grids[3] = {2048 / 4, 1536 / 4, 384 / 4};
    float* pin = xa; float* pout = xb;
    for (int layer = 0; layer < 4; layer++) {
        for (int sc = 0; sc < 3; sc++) {
            k_dgcn<<<grids[sc], 256>>>(pin, pout,
                                       dgcn_w + (size_t)(sc * 4 + layer) * 128 * 64,
                                       dgcn_b + (size_t)(sc * 4 + layer) * 64,
                                       edge0, edge1, edge2, sc);
        }
        float* tmp = pin; pin = pout; pout = tmp;
    }
    // after 4 swaps the final features are back in g_xa

    k_head<<<(kNR + 7) / 8, 256>>>(dgcn_hw, dgcn_hb, target0, target1, target2, out);
    k_final<<<1, 32>>>(out);
}

// round 10
// speedup vs baseline: 1.6767x; 1.6767x over previous
#include <cuda_runtime.h>
#include <math.h>

// ---------------------------------------------------------------------------
// VanishingNet full pipeline, fp32, NHWC.
// R10: scalar conv (R6 form, proven) + fused ht-BN stats; dgcn as
// U/V-precompute GEMM + trivial edge max; warp-gather hough/sphere.
// ---------------------------------------------------------------------------

#define kB     2
#define kC     128
#define kNPIX  16384
#define kHTH   184
#define kHTW   180
#define kNBINS (kHTH * kHTW)   /* 33120 */
#define kSN    1984            /* per-batch node rows: 1024 + 768 + 192 */
#define kNR    (kB * kSN)      /* 3968 */
#define kEPS   1e-5f

// --------------------------- scratch (device globals) ----------------------
__device__ float g_xT [kB * kNPIX * kC];    // BN+ReLU image, [b][p][c]
__device__ float g_ht [kB * kNBINS * kC];   // Hough map, [b][bin][c]
__device__ float g_hc [kB * kNBINS * kC];   // conv out, [b][bin][c]
__device__ float g_sph[kNR * kC];           // sphere features [r][c]
__device__ float g_y  [kNR * 64];           // sconv pre-BN
__device__ float g_xa [kNR * 64];           // dgcn ping
__device__ float g_xb [kNR * 64];           // dgcn pong
__device__ float g_uv [kNR * 128];          // dgcn U|V per layer
__device__ float g_simg[2 * kC];            // image BN stats
__device__ float g_sht [2 * kC];            // ht BN stats (atomics)
__device__ float g_ssc [2 * 192];           // sconv BN stats (atomics)
__device__ float g_bce [12];                // {sum_pos,sum_neg,npos,nneg} x3

__device__ __forceinline__ float warpSum(float v) {
    #pragma unroll
    for (int o = 16; o > 0; o >>= 1) v += __shfl_down_sync(0xffffffffu, v, o);
    return v;
}
__device__ __forceinline__ float fcomp(const float4& a, int u) {
    return u == 0 ? a.x : (u == 1 ? a.y : (u == 2 ? a.z : a.w));
}

// --------------------------- k0: zero accumulators --------------------------
__global__ void k_zero() {
    int t = threadIdx.x;
    if (t < 2 * kC) { g_sht[t] = 0.f; }
    if (t < 384)    { g_ssc[t] = 0.f; }
    if (t < 12)     { g_bce[t] = 0.f; }
}

// --------------------------- k1: image BN stats ------------------------------
__global__ __launch_bounds__(256) void k_img_stats(const float* __restrict__ img) {
    int c = blockIdx.x, t = threadIdx.x;
    float s = 0.f, s2 = 0.f;
    for (int b = 0; b < kB; b++) {
        const float* p = img + (size_t)(b * kC + c) * kNPIX;
        for (int i = t; i < kNPIX; i += 256) { float v = p[i]; s += v; s2 += v * v; }
    }
    __shared__ float rs[8], rs2[8];
    int lane = t & 31, w = t >> 5;
    s = warpSum(s); s2 = warpSum(s2);
    if (lane == 0) { rs[w] = s; rs2[w] = s2; }
    __syncthreads();
    if (t == 0) {
        float a = 0.f, a2 = 0.f;
        #pragma unroll
        for (int i = 0; i < 8; i++) { a += rs[i]; a2 += rs2[i]; }
        g_simg[c] = a; g_simg[kC + c] = a2;
    }
}

// ---------------- k2: BN + ReLU + transpose to pixel-major -------------------
__global__ void k_bnt(const float* __restrict__ img, const float* __restrict__ gam,
                      const float* __restrict__ bet) {
    __shared__ float tile[32][33];
    int p0 = blockIdx.x * 32, c0 = blockIdx.y * 32, b = blockIdx.z;
    int tx = threadIdx.x, ty = threadIdx.y;
    #pragma unroll
    for (int i = 0; i < 4; i++) {
        int c = c0 + ty * 4 + i;
        tile[ty * 4 + i][tx] = img[(size_t)(b * kC + c) * kNPIX + p0 + tx];
    }
    __syncthreads();
    int c = c0 + tx;
    float mean = g_simg[c] * (1.f / 32768.f);
    float var  = g_simg[kC + c] * (1.f / 32768.f) - mean * mean;
    float sc = gam[c] * rsqrtf(var + kEPS);
    float bi = bet[c] - mean * sc;
    #pragma unroll
    for (int i = 0; i < 4; i++) {
        int p = p0 + ty * 4 + i;
        float v = tile[tx][ty * 4 + i];
        g_xT[(size_t)(b * kNPIX + p) * kC + c] = fmaxf(sc * v + bi, 0.f);
    }
}

// --------------------------- k3: Hough voting (warp per bin) -----------------
__global__ __launch_bounds__(256) void k_hough(const int* __restrict__ hidx,
                                               const float* __restrict__ hw) {
    int gw = blockIdx.x * 8 + (threadIdx.x >> 5);   // 0 .. 66239
    int lane = threadIdx.x & 31;
    int b = gw / kNBINS, bin = gw - b * kNBINS;
    int   iv = 0; float wv = 0.f;
    if (lane < 8) { iv = hidx[bin * 8 + lane]; wv = hw[bin * 8 + lane]; }
    const float4* xb = (const float4*)(g_xT + (size_t)b * kNPIX * kC);
    float4 acc = make_float4(0.f, 0.f, 0.f, 0.f);
    #pragma unroll
    for (int k = 0; k < 8; k++) {
        int   ik = __shfl_sync(0xffffffffu, iv, k);
        float wk = __shfl_sync(0xffffffffu, wv, k);
        float4 v = xb[(size_t)ik * 32 + lane];
        acc.x += wk * v.x; acc.y += wk * v.y; acc.z += wk * v.z; acc.w += wk * v.w;
    }
    ((float4*)g_ht)[(size_t)(b * kNBINS + bin) * 32 + lane] = acc;
}

// --------------------------- k4: 3x3 conv (scalar, R6 form) ------------------
// Block: 64 px (one y row) x 128 cout. Thread: 8 px x 4 cout. cin chunks of 32.
// Epilogue: block-reduced BN stats of outputs -> atomics into g_sht.
__global__ __launch_bounds__(256, 2) void k_conv(const float* __restrict__ Wc) {
    __shared__ __align__(16) float sIn[3 * 66 * 32];  // [kh][px 0..65][ci]
    __shared__ __align__(16) float sW[32 * 128];      // [ci][co]
    const int t   = threadIdx.x;
    const int xc0 = blockIdx.x * 64;
    const int y   = blockIdx.y;
    const int b   = blockIdx.z;
    const int cog = t & 31;          // lane
    const int pg  = t >> 5;          // warp = pixel phase 0..7
    const int co0 = cog << 2;
    float acc[8][4];
    #pragma unroll
    for (int m = 0; m < 8; m++)
        #pragma unroll
        for (int j = 0; j < 4; j++) acc[m][j] = 0.f;

    for (int cc = 0; cc < 128; cc += 32) {
        __syncthreads();   // protect sIn from previous chunk's readers
        for (int i = t; i < 3 * 66 * 32; i += 256) {
            int ci = i & 31; int r2 = i >> 5; int px = r2 % 66; int kh = r2 / 66;
            int gy = y + kh - 1, gx = xc0 + px - 1;
            float v = 0.f;
            if ((unsigned)gy < kHTH && (unsigned)gx < kHTW)
                v = g_ht[(size_t)(b * kNBINS + gy * kHTW + gx) * kC + cc + ci];
            sIn[i] = v;
        }
        #pragma unroll 1
        for (int tap = 0; tap < 9; tap++) {
            __syncthreads();   // sIn ready / previous sW consumed
            const float* wp = Wc + (size_t)(tap * kC + cc) * kC;
            for (int i = t; i < 4096; i += 256) sW[i] = wp[i];
            __syncthreads();
            const int kh = tap / 3, kw = tap - kh * 3;
            const float* inRow = &sIn[(kh * 66 + kw + pg) * 32];
            #pragma unroll
            for (int c4 = 0; c4 < 8; c4++) {
                float4 A[8];
                #pragma unroll
                for (int m = 0; m < 8; m++)
                    A[m] = *reinterpret_cast<const float4*>(inRow + (m << 8) + (c4 << 2));
                #pragma unroll
                for (int u = 0; u < 4; u++) {
                    float4 w = *reinterpret_cast<const float4*>(&sW[(c4 * 4 + u) * 128 + co0]);
                    #pragma unroll
                    for (int m = 0; m < 8; m++) {
                        float a = fcomp(A[m], u);
                        acc[m][0] += a * w.x;
                        acc[m][1] += a * w.y;
                        acc[m][2] += a * w.z;
                        acc[m][3] += a * w.w;
                    }
                }
            }
        }
    }
    float s1[4] = {0.f, 0.f, 0.f, 0.f};
    float s2[4] = {0.f, 0.f, 0.f, 0.f};
    #pragma unroll
    for (int m = 0; m < 8; m++) {
        int gx = xc0 + pg + 8 * m;
        if (gx < kHTW) {
            float4 o = make_float4(acc[m][0], acc[m][1], acc[m][2], acc[m][3]);
            *reinterpret_cast<float4*>(
                &g_hc[(size_t)(b * kNBINS + y * kHTW + gx) * kC + co0]) = o;
            #pragma unroll
            for (int j = 0; j < 4; j++) {
                float v = acc[m][j];
                s1[j] += v; s2[j] += v * v;
            }
        }
    }
    // block reduction of stats via sW (all FMA readers are done with it after
    // this barrier)
    __syncthreads();
    #pragma unroll
    for (int j = 0; j < 4; j++) {
        sW[pg * 128 + co0 + j]        = s1[j];
        sW[1024 + pg * 128 + co0 + j] = s2[j];
    }
    __syncthreads();
    if (t < 128) {
        float a = 0.f, a2 = 0.f;
        #pragma unroll
        for (int p = 0; p < 8; p++) {
            a  += sW[p * 128 + t];
            a2 += sW[1024 + p * 128 + t];
        }
        atomicAdd(&g_sht[t], a);
        atomicAdd(&g_sht[kC + t], a2);
    }
}

// ---------------- k6: sphere gather (warp per node, fused ht BN+ReLU) --------
__global__ __launch_bounds__(256) void k_sphere(const float* __restrict__ gam,
                                                const float* __restrict__ bet,
                                                const int* __restrict__ sph_idx,
                                                const float* __restrict__ sph_w,
                                                const int* __restrict__ ind0,
                                                const int* __restrict__ ind1,
                                                const int* __restrict__ ind2) {
    int gw = blockIdx.x * 8 + (threadIdx.x >> 5);   // 0 .. kNR-1
    int lane = threadIdx.x & 31;
    int b = gw / kSN, s = gw - b * kSN;
    int sp;
    if (s < 1024)      sp = ind0[b * 1024 + s];
    else if (s < 1792) sp = ind1[b * 768 + (s - 1024)];
    else               sp = ind2[b * 192 + (s - 1792)];
    int   iv = 0; float wv = 0.f;
    if (lane < 16) { iv = sph_idx[sp * 16 + lane]; wv = sph_w[sp * 16 + lane]; }
    const float inv = 1.f / (float)(kB * kNBINS);
    float4 s1 = ((const float4*)g_sht)[lane];
    float4 s2 = ((const float4*)g_sht)[32 + lane];
    float4 g4 = ((const float4*)gam)[lane];
    float4 b4 = ((const float4*)bet)[lane];
    float4 sc4, bi4;
    {
        float m, v;
        m = s1.x * inv; v = s2.x * inv - m * m; sc4.x = g4.x * rsqrtf(v + kEPS); bi4.x = b4.x - m * sc4.x;
        m = s1.y * inv; v = s2.y * inv - m * m; sc4.y = g4.y * rsqrtf(v + kEPS); bi4.y = b4.y - m * sc4.y;
        m = s1.z * inv; v = s2.z * inv - m * m; sc4.z = g4.z * rsqrtf(v + kEPS); bi4.z = b4.z - m * sc4.z;
        m = s1.w * inv; v = s2.w * inv - m * m; sc4.w = g4.w * rsqrtf(v + kEPS); bi4.w = b4.w - m * sc4.w;
    }
    const float4* base = (const float4*)(g_hc + (size_t)b * kNBINS * kC);
    float4 acc = make_float4(0.f, 0.f, 0.f, 0.f);
    #pragma unroll
    for (int k = 0; k < 16; k++) {
        int   ik = __shfl_sync(0xffffffffu, iv, k);
        float wk = __shfl_sync(0xffffffffu, wv, k);
        float4 v = base[(size_t)ik * 32 + lane];
        acc.x += wk * fmaxf(sc4.x * v.x + bi4.x, 0.f);
        acc.y += wk * fmaxf(sc4.y * v.y + bi4.y, 0.f);
        acc.z += wk * fmaxf(sc4.z * v.z + bi4.z, 0.f);
        acc.w += wk * fmaxf(sc4.w * v.w + bi4.w, 0.f);
    }
    ((float4*)g_sph)[(size_t)(b * kSN + s) * 32 + lane] = acc;
}

// --------------------------- k7: sconv (1x1 conv) + stats --------------------
__global__ __launch_bounds__(128) void k_sconv(const float* __restrict__ w_sc,
                                               const float* __restrict__ b_sc) {
    __shared__ float sWt[128 * 64];   // [c][o]
    __shared__ float sRow[2][128];
    int bx = blockIdx.x;
    int b = bx / 31, u = bx % 31;
    int sc, rbase;
    if (u < 16)      { sc = 0; rbase = b * kSN + u * 64; }
    else if (u < 28) { sc = 1; rbase = b * kSN + 1024 + (u - 16) * 64; }
    else             { sc = 2; rbase = b * kSN + 1792 + (u - 28) * 64; }
    int t = threadIdx.x, o = t & 63, half = t >> 6;
    for (int i = t; i < 8192; i += 128) {
        int c = i >> 6, oo = i & 63;
        sWt[i] = w_sc[(size_t)(sc * 64 + oo) * 128 + c];
    }
    __syncthreads();
    float bo = b_sc[sc * 64 + o];
    float ls = 0.f, ls2 = 0.f;
    for (int r0 = 0; r0 < 64; r0 += 2) {
        __syncthreads();
        sRow[0][t] = g_sph[(size_t)(rbase + r0) * 128 + t];
        sRow[1][t] = g_sph[(size_t)(rbase + r0 + 1) * 128 + t];
        __syncthreads();
        const float* rp = sRow[half];
        float acc = bo;
        #pragma unroll 8
        for (int c = 0; c < 128; c++) acc += rp[c] * sWt[c * 64 + o];
        g_y[(size_t)(rbase + r0 + half) * 64 + o] = acc;
        ls += acc; ls2 += acc * acc;
    }
    atomicAdd(&g_ssc[sc * 64 + o], ls);
    atomicAdd(&g_ssc[192 + sc * 64 + o], ls2);
}

// --------------------------- k8: sconv BN + ReLU -----------------------------
__global__ void k_scbn(const float* __restrict__ gam, const float* __restrict__ bet) {
    int idx = blockIdx.x * blockDim.x + threadIdx.x;
    if (idx >= kNR * 64) return;
    int r = idx >> 6, o = idx & 63;
    int s = r % kSN;
    int sc = (s < 1024) ? 0 : (s < 1792 ? 1 : 2);
    float cnt = (sc == 0) ? 2048.f : (sc == 1 ? 1536.f : 384.f);
    float mean = g_ssc[sc * 64 + o] / cnt;
    float var  = g_ssc[192 + sc * 64 + o] / cnt - mean * mean;
    float scv = gam[sc * 64 + o] * rsqrtf(var + kEPS);
    float bi  = bet[sc * 64 + o] - mean * scv;
    g_xa[idx] = fmaxf(scv * g_y[idx] + bi, 0.f);
}

// ------------------- k9a: dgcn per-layer GEMM: [U | V] -----------------------
// U = X @ (W1 - W2) + b, V = X @ W2. Block = 16 rows, 128 threads (one out col
// of the 128-wide [U|V] each). All 16 rows of a block lie in one scale region.
__global__ __launch_bounds__(128) void k_dgcn_gemm(const float* __restrict__ xin,
                                                   const float* __restrict__ dgw,
                                                   const float* __restrict__ dgb,
                                                   int layer) {
    __shared__ __align__(16) float sWc[64 * 128];  // [c][ U(0..63) | V(64..127) ]
    __shared__ __align__(16) float sX[16 * 64];
    int t = threadIdx.x;
    int r0 = blockIdx.x * 16;
    int b = r0 / kSN, s = r0 - b * kSN;
    int sc = (s < 1024) ? 0 : (s < 1792 ? 1 : 2);
    const float* W  = dgw + (size_t)(sc * 4 + layer) * 8192;
    const float* bi = dgb + (size_t)(sc * 4 + layer) * 64;
    for (int i = t; i < 4096; i += 128) {
        int c = i >> 6, o = i & 63;
        float w2 = W[4096 + i];
        sWc[c * 128 + o]      = W[i] - w2;
        sWc[c * 128 + 64 + o] = w2;
    }
    for (int i = t; i < 1024; i += 128) sX[i] = xin[(size_t)r0 * 64 + i];
    __syncthreads();
    float acc[16];
    float binit = (t < 64) ? bi[t] : 0.f;
    #pragma unroll
    for (int rr = 0; rr < 16; rr++) acc[rr] = binit;
    #pragma unroll 4
    for (int c4 = 0; c4 < 16; c4++) {
        float w0 = sWc[(c4 * 4 + 0) * 128 + t];
        float w1 = sWc[(c4 * 4 + 1) * 128 + t];
        float w2 = sWc[(c4 * 4 + 2) * 128 + t];
        float w3 = sWc[(c4 * 4 + 3) * 128 + t];
        #pragma unroll
        for (int rr = 0; rr < 16; rr++) {
            float4 xv = *reinterpret_cast<const float4*>(&sX[rr * 64 + c4 * 4]);
            acc[rr] += xv.x * w0 + xv.y * w1 + xv.z * w2 + xv.w * w3;
        }
    }
    #pragma unroll
    for (int rr = 0; rr < 16; rr++)
        g_uv[(size_t)(r0 + rr) * 128 + t] = acc[rr];
}

// ------------------- k9b: dgcn edge phase: max_k relu(U_c + V_n) -------------
// Warp per node; lane covers channels (lane, lane+32).
__global__ __launch_bounds__(256) void k_edge(float* __restrict__ xout,
                                              const int* __restrict__ e0,
                                              const int* __restrict__ e1,
                                              const int* __restrict__ e2) {
    int r = blockIdx.x * 8 + (threadIdx.x >> 5);
    int lane = threadIdx.x & 31;
    int b = r / kSN, s = r - b * kSN;
    int rbase, enBase;
    const int* E;
    if (s < 1024) {
        rbase = b * kSN;
        E = e0; enBase = b * 2 * 8192 + 8192 + s * 8;
    } else if (s < 1792) {
        int q = s - 1024, v = q >> 8, j = q & 255, g = b * 3 + v;
        rbase = b * kSN + 1024 + v * 256;
        E = e1; enBase = g * 2 * 2048 + 2048 + j * 8;
    } else {
        int q = s - 1792, v = q >> 6, j = q & 63, g = b * 3 + v;
        rbase = b * kSN + 1792 + v * 64;
        E = e2; enBase = g * 2 * 512 + 512 + j * 8;
    }
    int nv = (lane < 8) ? E[enBase + lane] : 0;
    float u0 = g_uv[(size_t)r * 128 + lane];
    float u1 = g_uv[(size_t)r * 128 + 32 + lane];
    float m0 = 0.f, m1 = 0.f;     // relu clamps at 0 anyway
    #pragma unroll
    for (int k = 0; k < 8; k++) {
        int n = rbase + __shfl_sync(0xffffffffu, nv, k);
        float v0 = g_uv[(size_t)n * 128 + 64 + lane];
        float v1 = g_uv[(size_t)n * 128 + 96 + lane];
        m0 = fmaxf(m0, u0 + v0);
        m1 = fmaxf(m1, u1 + v1);
    }
    xout[(size_t)r * 64 + lane]      = m0;
    xout[(size_t)r * 64 + 32 + lane] = m1;
}

// --------------------------- k10: head + BCE accumulation --------------------
__global__ __launch_bounds__(256) void k_head(const float* __restrict__ hw,
                                              const float* __restrict__ hb,
                                              const int* __restrict__ t0,
                                              const int* __restrict__ t1,
                                              const int* __restrict__ t2,
                                              float* __restrict__ out) {
    int t = threadIdx.x;
    int warp = t >> 5, lane = t & 31;
    int r = blockIdx.x * 8 + warp;
    if (r >= kNR) return;
    int b = r / kSN, s = r - b * kSN;
    int sc, tgt;
    if (s < 1024)      { sc = 0; tgt = t0[b * 1024 + s]; }
    else if (s < 1792) { sc = 1; int q = s - 1024; tgt = t1[(b * 3 + (q >> 8)) * 256 + (q & 255)]; }
    else               { sc = 2; int q = s - 1792; tgt = t2[(b * 3 + (q >> 6)) * 64 + (q & 63)]; }
    const float* x = g_xa + (size_t)r * 64;
    float partial = x[lane] * hw[sc * 64 + lane] + x[lane + 32] * hw[sc * 64 + lane + 32];
    partial = warpSum(partial);
    if (lane == 0) {
        float z = partial + hb[sc];
        out[6 + r] = 1.f / (1.f + expf(-z));
        float l = fmaxf(z, 0.f) - z * (float)tgt + log1pf(expf(-fabsf(z)));
        if (tgt > 0) { atomicAdd(&g_bce[sc * 4 + 0], l); atomicAdd(&g_bce[sc * 4 + 2], 1.f); }
        else         { atomicAdd(&g_bce[sc * 4 + 1], l); atomicAdd(&g_bce[sc * 4 + 3], 1.f); }
    }
}

// --------------------------- k11: finalize losses ----------------------------
__global__ void k_final(float* __restrict__ out) {
    int sc = threadIdx.x;
    if (sc < 3) {
        float np = fmaxf(g_bce[sc * 4 + 2], 1.f);
        float nn = fmaxf(g_bce[sc * 4 + 3], 1.f);
        out[sc * 2 + 0] = g_bce[sc * 4 + 0] / np;
        out[sc * 2 + 1] = g_bce[sc * 4 + 1] / nn;
    }
}

// ---------------------------------------------------------------------------
extern "C" void kernel_launch(void* const* d_in, const int* in_sizes, int n_in,
                              void* d_out, int out_size) {
    const float* image      = (const float*)d_in[0];
    const float* bn_gamma   = (const float*)d_in[1];
    const float* bn_beta    = (const float*)d_in[2];
    const int*   ht_idx     = (const int*)  d_in[3];
    const float* ht_w       = (const float*)d_in[4];
    const float* w_htconv   = (const float*)d_in[5];
    const float* htbn_gamma = (const float*)d_in[6];
    const float* htbn_beta  = (const float*)d_in[7];
    const int*   sph_idx    = (const int*)  d_in[8];
    const float* sph_w      = (const float*)d_in[9];
    const float* w_sc       = (const float*)d_in[10];
    const float* b_sc       = (const float*)d_in[11];
    const float* scbn_gamma = (const float*)d_in[12];
    const float* scbn_beta  = (const float*)d_in[13];
    const float* dgcn_w     = (const float*)d_in[14];
    const float* dgcn_b     = (const float*)d_in[15];
    const float* dgcn_hw    = (const float*)d_in[16];
    const float* dgcn_hb    = (const float*)d_in[17];
    const int*   ind0       = (const int*)  d_in[18];
    const int*   ind1       = (const int*)  d_in[19];
    const int*   ind2       = (const int*)  d_in[20];
    const int*   edge0      = (const int*)  d_in[21];
    const int*   edge1      = (const int*)  d_in[22];
    const int*   edge2      = (const int*)  d_in[23];
    const int*   target0    = (const int*)  d_in[24];
    const int*   target1    = (const int*)  d_in[25];
    const int*   target2    = (const int*)  d_in[26];
    float* out = (float*)d_out;

    k_zero<<<1, 512>>>();
    k_img_stats<<<kC, 256>>>(image);
    k_bnt<<<dim3(kNPIX / 32, kC / 32, kB), dim3(32, 8)>>>(image, bn_gamma, bn_beta);
    k_hough<<<(kB * kNBINS) / 8, 256>>>(ht_idx, ht_w);
    k_conv<<<dim3(3, kHTH, kB), 256>>>(w_htconv);
    k_sphere<<<kNR / 8, 256>>>(htbn_gamma, htbn_beta, sph_idx, sph_w,
                               ind0, ind1, ind2);
    k_sconv<<<62, 128>>>(w_sc, b_sc);
    k_scbn<<<(kNR * 64 + 255) / 256, 256>>>(scbn_gamma, scbn_beta);

    // dgcn: 4 layers; per layer one GEMM ([U|V]) + one edge/max pass.
    float* xa; float* xb;
    cudaGetSymbolAddress((void**)&xa, g_xa);
    cudaGetSymbolAddress((void**)&xb, g_xb);
    float* pin = xa; float* pout = xb;
    for (int layer = 0; layer < 4; layer++) {
        k_dgcn_gemm<<<kNR / 16, 128>>>(pin, dgcn_w, dgcn_b, layer);
        k_edge<<<kNR / 8, 256>>>(pout, edge0, edge1, edge2);
        float* tmp = pin; pin = pout; pout = tmp;
    }
    // after 4 swaps the final features are back in g_xa

    k_head<<<(kNR + 7) / 8, 256>>>(dgcn_hw, dgcn_hb, target0, target1, target2, out);
    k_final<<<1, 32>>>(out);
}

// round 13
// speedup vs baseline: 3.3841x; 2.0183x over previous
#include <cuda_runtime.h>
#include <cuda_bf16.h>
#include <math.h>
#include <stdint.h>

// ---------------------------------------------------------------------------
// VanishingNet full pipeline. R13: mma.sync bf16 hi/lo-split conv (legacy
// tensor pipe; tcgen05 is rejected by the compute_103 virtual target).
// Everything else: R10 (715us) baseline.
// ---------------------------------------------------------------------------

#define kB     2
#define kC     128
#define kNPIX  16384
#define kHTH   184
#define kHTW   180
#define kNBINS (kHTH * kHTW)   /* 33120 */
#define kSN    1984
#define kNR    (kB * kSN)      /* 3968 */
#define kEPS   1e-5f

// --------------------------- scratch (device globals) ----------------------
__device__ float g_xT [kB * kNPIX * kC];
__device__ float g_ht [kB * kNBINS * kC];
__device__ float g_hc [kB * kNBINS * kC];
__device__ float g_sph[kNR * kC];
__device__ float g_y  [kNR * 64];
__device__ float g_xa [kNR * 64];
__device__ float g_xb [kNR * 64];
__device__ float g_uv [kNR * 128];
__device__ float g_simg[2 * kC];
__device__ float g_sht [2 * kC];
__device__ float g_ssc [2 * 192];
__device__ float g_bce [12];
// pre-swizzled bf16 weight tiles: [tap][ hi 32KB | lo 32KB ], layout [co][ci]
__device__ __align__(16) unsigned char g_wB[9 * 65536];

__device__ __forceinline__ float warpSum(float v) {
    #pragma unroll
    for (int o = 16; o > 0; o >>= 1) v += __shfl_down_sync(0xffffffffu, v, o);
    return v;
}
__device__ __forceinline__ uint32_t smem_u32(const void* p) {
    uint32_t a;
    asm("{ .reg .u64 t; cvta.to.shared.u64 t, %1; cvt.u32.u64 %0, t; }"
        : "=r"(a) : "l"(p));
    return a;
}
__device__ __forceinline__ void ldsm4(uint32_t* r, uint32_t addr) {
    asm volatile("ldmatrix.sync.aligned.m8n8.x4.shared.b16 {%0,%1,%2,%3}, [%4];"
                 : "=r"(r[0]), "=r"(r[1]), "=r"(r[2]), "=r"(r[3]) : "r"(addr));
}
__device__ __forceinline__ void mma16816(float* d, const uint32_t* a,
                                         const uint32_t* b) {
    asm volatile(
        "mma.sync.aligned.m16n8k16.row.col.f32.bf16.bf16.f32 "
        "{%0,%1,%2,%3}, {%4,%5,%6,%7}, {%8,%9}, {%0,%1,%2,%3};"
        : "+f"(d[0]), "+f"(d[1]), "+f"(d[2]), "+f"(d[3])
        : "r"(a[0]), "r"(a[1]), "r"(a[2]), "r"(a[3]), "r"(b[0]), "r"(b[1]));
}

// --------------------------- k0: zero accumulators --------------------------
__global__ void k_zero() {
    int t = threadIdx.x;
    if (t < 2 * kC) { g_sht[t] = 0.f; }
    if (t < 384)    { g_ssc[t] = 0.f; }
    if (t < 12)     { g_bce[t] = 0.f; }
}

// --------------------------- k1: image BN stats ------------------------------
__global__ __launch_bounds__(256) void k_img_stats(const float* __restrict__ img) {
    int c = blockIdx.x, t = threadIdx.x;
    float s = 0.f, s2 = 0.f;
    for (int b = 0; b < kB; b++) {
        const float* p = img + (size_t)(b * kC + c) * kNPIX;
        for (int i = t; i < kNPIX; i += 256) { float v = p[i]; s += v; s2 += v * v; }
    }
    __shared__ float rs[8], rs2[8];
    int lane = t & 31, w = t >> 5;
    s = warpSum(s); s2 = warpSum(s2);
    if (lane == 0) { rs[w] = s; rs2[w] = s2; }
    __syncthreads();
    if (t == 0) {
        float a = 0.f, a2 = 0.f;
        #pragma unroll
        for (int i = 0; i < 8; i++) { a += rs[i]; a2 += rs2[i]; }
        g_simg[c] = a; g_simg[kC + c] = a2;
    }
}

// ---------------- k2: BN + ReLU + transpose to pixel-major -------------------
__global__ void k_bnt(const float* __restrict__ img, const float* __restrict__ gam,
                      const float* __restrict__ bet) {
    __shared__ float tile[32][33];
    int p0 = blockIdx.x * 32, c0 = blockIdx.y * 32, b = blockIdx.z;
    int tx = threadIdx.x, ty = threadIdx.y;
    #pragma unroll
    for (int i = 0; i < 4; i++) {
        int c = c0 + ty * 4 + i;
        tile[ty * 4 + i][tx] = img[(size_t)(b * kC + c) * kNPIX + p0 + tx];
    }
    __syncthreads();
    int c = c0 + tx;
    float mean = g_simg[c] * (1.f / 32768.f);
    float var  = g_simg[kC + c] * (1.f / 32768.f) - mean * mean;
    float sc = gam[c] * rsqrtf(var + kEPS);
    float bi = bet[c] - mean * sc;
    #pragma unroll
    for (int i = 0; i < 4; i++) {
        int p = p0 + ty * 4 + i;
        float v = tile[tx][ty * 4 + i];
        g_xT[(size_t)(b * kNPIX + p) * kC + c] = fmaxf(sc * v + bi, 0.f);
    }
}

// --------------------------- k3: Hough voting (warp per bin) -----------------
__global__ __launch_bounds__(256) void k_hough(const int* __restrict__ hidx,
                                               const float* __restrict__ hw) {
    int gw = blockIdx.x * 8 + (threadIdx.x >> 5);
    int lane = threadIdx.x & 31;
    int b = gw / kNBINS, bin = gw - b * kNBINS;
    int   iv = 0; float wv = 0.f;
    if (lane < 8) { iv = hidx[bin * 8 + lane]; wv = hw[bin * 8 + lane]; }
    const float4* xb = (const float4*)(g_xT + (size_t)b * kNPIX * kC);
    float4 acc = make_float4(0.f, 0.f, 0.f, 0.f);
    #pragma unroll
    for (int k = 0; k < 8; k++) {
        int   ik = __shfl_sync(0xffffffffu, iv, k);
        float wk = __shfl_sync(0xffffffffu, wv, k);
        float4 v = xb[(size_t)ik * 32 + lane];
        acc.x += wk * v.x; acc.y += wk * v.y; acc.z += wk * v.z; acc.w += wk * v.w;
    }
    ((float4*)g_ht)[(size_t)(b * kNBINS + bin) * 32 + lane] = acc;
}

// ------------- k_wprep: weights -> pre-swizzled bf16 hi/lo B tiles -----------
// Layout per tap (matches conv smem image exactly): hi 32KB then lo 32KB;
// within a 32KB block: row = co (256B), 16B chunk index = (ci>>3) ^ (co&7).
__global__ void k_wprep(const float* __restrict__ W) {
    int i = blockIdx.x * 256 + threadIdx.x;
    if (i >= 9 * 16384) return;
    int tap = i >> 14, rem = i & 16383;
    int ci = rem >> 7, co = rem & 127;
    float w = W[((size_t)tap * 128 + ci) * 128 + co];
    __nv_bfloat16 hi = __float2bfloat16(w);
    __nv_bfloat16 lo = __float2bfloat16(w - __bfloat162float(hi));
    int off = co * 256 + (((ci >> 3) ^ (co & 7)) << 4) + (ci & 7) * 2;
    *(__nv_bfloat16*)(g_wB + (size_t)tap * 65536 + off)         = hi;
    *(__nv_bfloat16*)(g_wB + (size_t)tap * 65536 + 32768 + off) = lo;
}

// --------------------------- k4: mma.sync conv -------------------------------
// CTA tile: M=128 px (2 y-rows x 64 x) x N=128 cout. 8 warps = 4M x 2N.
// A patch [4y][66x][128ci] hi/lo bf16 built once; 9 taps shift rows.
// Per (tap, k16): 3 bf16 products hi*hi + hi*lo + lo*hi.
#define PATCH_B   67584              /* 264 rows * 256 B */
#define SM_ALO    PATCH_B
#define SM_B      (2 * PATCH_B)      /* 135168 */
#define SMEM_CONV (2 * PATCH_B + 65536)   /* 200704 */
__global__ __launch_bounds__(256, 1) void k_conv() {
    extern __shared__ __align__(16) char smem[];
    const uint32_t sA = smem_u32(smem);
    const uint32_t sB = sA + SM_B;
    const int t    = threadIdx.x;
    const int wid  = t >> 5;
    const int lane = t & 31;
    const int x0   = blockIdx.x * 64;
    const int y0   = blockIdx.y * 2;
    const int b    = blockIdx.z;
    const int warpM = wid & 3;        // 0..3 -> m0 = warpM*32
    const int warpN = wid >> 2;       // 0..1 -> n0 = warpN*64

    // ---- build A patch (hi/lo split, swizzled) ----
    for (int i = t; i < 264 * 16; i += 256) {
        int row = i >> 4, ch = i & 15;
        int yy = row / 66, xx = row - yy * 66;
        int gy = y0 + yy - 1, gx = x0 + xx - 1;
        bool valid = ((unsigned)gy < kHTH) && ((unsigned)gx < kHTW);
        float4 v0 = make_float4(0.f, 0.f, 0.f, 0.f), v1 = v0;
        if (valid) {
            const float4* src = (const float4*)
                (g_ht + ((size_t)(b * kNBINS + gy * kHTW + gx) * kC + ch * 8));
            v0 = src[0]; v1 = src[1];
        }
        __nv_bfloat16 h[8], l[8];
        float f[8] = {v0.x, v0.y, v0.z, v0.w, v1.x, v1.y, v1.z, v1.w};
        #pragma unroll
        for (int j = 0; j < 8; j++) {
            h[j] = __float2bfloat16(f[j]);
            l[j] = __float2bfloat16(f[j] - __bfloat162float(h[j]));
        }
        int off = row * 256 + ((ch ^ (row & 7)) << 4);
        *(uint4*)(smem + off)          = *(uint4*)h;
        *(uint4*)(smem + SM_ALO + off) = *(uint4*)l;
    }

    float acc[2][8][4];
    #pragma unroll
    for (int mi = 0; mi < 2; mi++)
        #pragma unroll
        for (int nf = 0; nf < 8; nf++)
            #pragma unroll
            for (int j = 0; j < 4; j++) acc[mi][nf][j] = 0.f;

    // B ldmatrix address (tap-invariant): row = co, chunk from k-step
    const int browA = warpN * 64 + (lane & 7) + ((lane >> 4) << 3);
    const int bchsel = (lane >> 3) & 1;

    #pragma unroll 1
    for (int tap = 0; tap < 9; tap++) {
        const int kh = tap / 3, kw = tap - kh * 3;
        __syncthreads();   // patch ready (tap 0) / previous B consumed
        {
            const uint4* src = (const uint4*)(g_wB + (size_t)tap * 65536);
            uint4* dst = (uint4*)(smem + SM_B);
            for (int i = t; i < 4096; i += 256) dst[i] = src[i];
        }
        __syncthreads();
        #pragma unroll 1
        for (int s = 0; s < 8; s++) {
            uint32_t ah[2][4], al[2][4];
            #pragma unroll
            for (int mi = 0; mi < 2; mi++) {
                int m = warpM * 32 + mi * 16 + (lane & 15);
                int row = ((m >> 6) + kh) * 66 + (m & 63) + kw;
                int ch = (s * 2 + (lane >> 4)) ^ (row & 7);
                uint32_t ad = sA + row * 256 + (ch << 4);
                ldsm4(ah[mi], ad);
                ldsm4(al[mi], ad + SM_ALO);
            }
            #pragma unroll
            for (int np = 0; np < 4; np++) {
                int rowb = browA + np * 16;
                int chb = (s * 2 + bchsel) ^ (rowb & 7);
                uint32_t bd = sB + rowb * 256 + (chb << 4);
                uint32_t bh[4], bl[4];
                ldsm4(bh, bd);
                ldsm4(bl, bd + 32768);
                #pragma unroll
                for (int mi = 0; mi < 2; mi++) {
                    mma16816(acc[mi][np * 2],     ah[mi], bh);
                    mma16816(acc[mi][np * 2 + 1], ah[mi], bh + 2);
                    mma16816(acc[mi][np * 2],     ah[mi], bl);
                    mma16816(acc[mi][np * 2 + 1], ah[mi], bl + 2);
                    mma16816(acc[mi][np * 2],     al[mi], bh);
                    mma16816(acc[mi][np * 2 + 1], al[mi], bh + 2);
                }
            }
        }
    }

    // ---- epilogue: c-frag rows = lane>>2 (+8), cols = (lane&3)*2 ----
    #pragma unroll
    for (int mi = 0; mi < 2; mi++) {
        #pragma unroll
        for (int nf = 0; nf < 8; nf++) {
            int n = warpN * 64 + nf * 8 + (lane & 3) * 2;
            int m = warpM * 32 + mi * 16 + (lane >> 2);
            #pragma unroll
            for (int hh = 0; hh < 2; hh++) {
                int px = m + hh * 8;
                int gx = x0 + (px & 63);
                int gy = y0 + (px >> 6);
                if (gx < kHTW) {
                    float2 o = make_float2(acc[mi][nf][hh * 2],
                                           acc[mi][nf][hh * 2 + 1]);
                    *(float2*)(&g_hc[(size_t)(b * kNBINS + gy * kHTW + gx) * kC + n]) = o;
                }
            }
        }
    }
}

// --------------------------- k5: ht BN stats ---------------------------------
__global__ __launch_bounds__(128) void k_htstats() {
    int t = threadIdx.x, blk = blockIdx.x;
    int r0 = blk * 130, r1 = min(r0 + 130, kB * kNBINS);
    float s = 0.f, s2 = 0.f;
    for (int r = r0; r < r1; r++) {
        float v = g_hc[(size_t)r * kC + t];
        s += v; s2 += v * v;
    }
    atomicAdd(&g_sht[t], s);
    atomicAdd(&g_sht[kC + t], s2);
}

// ---------------- k6: sphere gather (warp per node, fused ht BN+ReLU) --------
__global__ __launch_bounds__(256) void k_sphere(const float* __restrict__ gam,
                                                const float* __restrict__ bet,
                                                const int* __restrict__ sph_idx,
                                                const float* __restrict__ sph_w,
                                                const int* __restrict__ ind0,
                                                const int* __restrict__ ind1,
                                                const int* __restrict__ ind2) {
    int gw = blockIdx.x * 8 + (threadIdx.x >> 5);
    int lane = threadIdx.x & 31;
    int b = gw / kSN, s = gw - b * kSN;
    int sp;
    if (s < 1024)      sp = ind0[b * 1024 + s];
    else if (s < 1792) sp = ind1[b * 768 + (s - 1024)];
    else               sp = ind2[b * 192 + (s - 1792)];
    int   iv = 0; float wv = 0.f;
    if (lane < 16) { iv = sph_idx[sp * 16 + lane]; wv = sph_w[sp * 16 + lane]; }
    const float inv = 1.f / (float)(kB * kNBINS);
    float4 s1 = ((const float4*)g_sht)[lane];
    float4 s2 = ((const float4*)g_sht)[32 + lane];
    float4 g4 = ((const float4*)gam)[lane];
    float4 b4 = ((const float4*)bet)[lane];
    float4 sc4, bi4;
    {
        float m, v;
        m = s1.x * inv; v = s2.x * inv - m * m; sc4.x = g4.x * rsqrtf(v + kEPS); bi4.x = b4.x - m * sc4.x;
        m = s1.y * inv; v = s2.y * inv - m * m; sc4.y = g4.y * rsqrtf(v + kEPS); bi4.y = b4.y - m * sc4.y;
        m = s1.z * inv; v = s2.z * inv - m * m; sc4.z = g4.z * rsqrtf(v + kEPS); bi4.z = b4.z - m * sc4.z;
        m = s1.w * inv; v = s2.w * inv - m * m; sc4.w = g4.w * rsqrtf(v + kEPS); bi4.w = b4.w - m * sc4.w;
    }
    const float4* base = (const float4*)(g_hc + (size_t)b * kNBINS * kC);
    float4 acc = make_float4(0.f, 0.f, 0.f, 0.f);
    #pragma unroll
    for (int k = 0; k < 16; k++) {
        int   ik = __shfl_sync(0xffffffffu, iv, k);
        float wk = __shfl_sync(0xffffffffu, wv, k);
        float4 v = base[(size_t)ik * 32 + lane];
        acc.x += wk * fmaxf(sc4.x * v.x + bi4.x, 0.f);
        acc.y += wk * fmaxf(sc4.y * v.y + bi4.y, 0.f);
        acc.z += wk * fmaxf(sc4.z * v.z + bi4.z, 0.f);
        acc.w += wk * fmaxf(sc4.w * v.w + bi4.w, 0.f);
    }
    ((float4*)g_sph)[(size_t)(b * kSN + s) * 32 + lane] = acc;
}

// --------------------------- k7: sconv (1x1 conv) + stats --------------------
__global__ __launch_bounds__(128) void k_sconv(const float* __restrict__ w_sc,
                                               const float* __restrict__ b_sc) {
    __shared__ float sWt[128 * 64];
    __shared__ float sRow[2][128];
    int bx = blockIdx.x;
    int b = bx / 31, u = bx % 31;
    int sc, rbase;
    if (u < 16)      { sc = 0; rbase = b * kSN + u * 64; }
    else if (u < 28) { sc = 1; rbase = b * kSN + 1024 + (u - 16) * 64; }
    else             { sc = 2; rbase = b * kSN + 1792 + (u - 28) * 64; }
    int t = threadIdx.x, o = t & 63, half = t >> 6;
    for (int i = t; i < 8192; i += 128) {
        int c = i >> 6, oo = i & 63;
        sWt[i] = w_sc[(size_t)(sc * 64 + oo) * 128 + c];
    }
    __syncthreads();
    float bo = b_sc[sc * 64 + o];
    float ls = 0.f, ls2 = 0.f;
    for (int r0 = 0; r0 < 64; r0 += 2) {
        __syncthreads();
        sRow[0][t] = g_sph[(size_t)(rbase + r0) * 128 + t];
        sRow[1][t] = g_sph[(size_t)(rbase + r0 + 1) * 128 + t];
        __syncthreads();
        const float* rp = sRow[half];
        float acc = bo;
        #pragma unroll 8
        for (int c = 0; c < 128; c++) acc += rp[c] * sWt[c * 64 + o];
        g_y[(size_t)(rbase + r0 + half) * 64 + o] = acc;
        ls += acc; ls2 += acc * acc;
    }
    atomicAdd(&g_ssc[sc * 64 + o], ls);
    atomicAdd(&g_ssc[192 + sc * 64 + o], ls2);
}

// --------------------------- k8: sconv BN + ReLU -----------------------------
__global__ void k_scbn(const float* __restrict__ gam, const float* __restrict__ bet) {
    int idx = blockIdx.x * blockDim.x + threadIdx.x;
    if (idx >= kNR * 64) return;
    int r = idx >> 6, o = idx & 63;
    int s = r % kSN;
    int sc = (s < 1024) ? 0 : (s < 1792 ? 1 : 2);
    float cnt = (sc == 0) ? 2048.f : (sc == 1 ? 1536.f : 384.f);
    float mean = g_ssc[sc * 64 + o] / cnt;
    float var  = g_ssc[192 + sc * 64 + o] / cnt - mean * mean;
    float scv = gam[sc * 64 + o] * rsqrtf(var + kEPS);
    float bi  = bet[sc * 64 + o] - mean * scv;
    g_xa[idx] = fmaxf(scv * g_y[idx] + bi, 0.f);
}

// ------------------- k9a: dgcn per-layer GEMM: [U | V] -----------------------
__global__ __launch_bounds__(128) void k_dgcn_gemm(const float* __restrict__ xin,
                                                   const float* __restrict__ dgw,
                                                   const float* __restrict__ dgb,
                                                   int layer) {
    __shared__ __align__(16) float sWc[64 * 128];
    __shared__ __align__(16) float sX[16 * 64];
    int t = threadIdx.x;
    int r0 = blockIdx.x * 16;
    int b = r0 / kSN, s = r0 - b * kSN;
    int sc = (s < 1024) ? 0 : (s < 1792 ? 1 : 2);
    const float* W  = dgw + (size_t)(sc * 4 + layer) * 8192;
    const float* bi = dgb + (size_t)(sc * 4 + layer) * 64;
    for (int i = t; i < 4096; i += 128) {
        int c = i >> 6, o = i & 63;
        float w2 = W[4096 + i];
        sWc[c * 128 + o]      = W[i] - w2;
        sWc[c * 128 + 64 + o] = w2;
    }
    for (int i = t; i < 1024; i += 128) sX[i] = xin[(size_t)r0 * 64 + i];
    __syncthreads();
    float acc[16];
    float binit = (t < 64) ? bi[t] : 0.f;
    #pragma unroll
    for (int rr = 0; rr < 16; rr++) acc[rr] = binit;
    #pragma unroll 4
    for (int c4 = 0; c4 < 16; c4++) {
        float w0 = sWc[(c4 * 4 + 0) * 128 + t];
        float w1 = sWc[(c4 * 4 + 1) * 128 + t];
        float w2 = sWc[(c4 * 4 + 2) * 128 + t];
        float w3 = sWc[(c4 * 4 + 3) * 128 + t];
        #pragma unroll
        for (int rr = 0; rr < 16; rr++) {
            float4 xv = *reinterpret_cast<const float4*>(&sX[rr * 64 + c4 * 4]);
            acc[rr] += xv.x * w0 + xv.y * w1 + xv.z * w2 + xv.w * w3;
        }
    }
    #pragma unroll
    for (int rr = 0; rr < 16; rr++)
        g_uv[(size_t)(r0 + rr) * 128 + t] = acc[rr];
}

// ------------------- k9b: dgcn edge phase: max_k relu(U_c + V_n) -------------
__global__ __launch_bounds__(256) void k_edge(float* __restrict__ xout,
                                              const int* __restrict__ e0,
                                              const int* __restrict__ e1,
                                              const int* __restrict__ e2) {
    int r = blockIdx.x * 8 + (threadIdx.x >> 5);
    int lane = threadIdx.x & 31;
    int b = r / kSN, s = r - b * kSN;
    int rbase, enBase;
    const int* E;
    if (s < 1024) {
        rbase = b * kSN;
        E = e0; enBase = b * 2 * 8192 + 8192 + s * 8;
    } else if (s < 1792) {
        int q = s - 1024, v = q >> 8, j = q & 255, g = b * 3 + v;
        rbase = b * kSN + 1024 + v * 256;
        E = e1; enBase = g * 2 * 2048 + 2048 + j * 8;
    } else {
        int q = s - 1792, v = q >> 6, j = q & 63, g = b * 3 + v;
        rbase = b * kSN + 1792 + v * 64;
        E = e2; enBase = g * 2 * 512 + 512 + j * 8;
    }
    int nv = (lane < 8) ? E[enBase + lane] : 0;
    float u0 = g_uv[(size_t)r * 128 + lane];
    float u1 = g_uv[(size_t)r * 128 + 32 + lane];
    float m0 = 0.f, m1 = 0.f;
    #pragma unroll
    for (int k = 0; k < 8; k++) {
        int n = rbase + __shfl_sync(0xffffffffu, nv, k);
        float v0 = g_uv[(size_t)n * 128 + 64 + lane];
        float v1 = g_uv[(size_t)n * 128 + 96 + lane];
        m0 = fmaxf(m0, u0 + v0);
        m1 = fmaxf(m1, u1 + v1);
    }
    xout[(size_t)r * 64 + lane]      = m0;
    xout[(size_t)r * 64 + 32 + lane] = m1;
}

// --------------------------- k10: head + BCE accumulation --------------------
__global__ __launch_bounds__(256) void k_head(const float* __restrict__ hw,
                                              const float* __restrict__ hb,
                                              const int* __restrict__ t0,
                                              const int* __restrict__ t1,
                                              const int* __restrict__ t2,
                                              float* __restrict__ out) {
    int t = threadIdx.x;
    int warp = t >> 5, lane = t & 31;
    int r = blockIdx.x * 8 + warp;
    if (r >= kNR) return;
    int b = r / kSN, s = r - b * kSN;
    int sc, tgt;
    if (s < 1024)      { sc = 0; tgt = t0[b * 1024 + s]; }
    else if (s < 1792) { sc = 1; int q = s - 1024; tgt = t1[(b * 3 + (q >> 8)) * 256 + (q & 255)]; }
    else               { sc = 2; int q = s - 1792; tgt = t2[(b * 3 + (q >> 6)) * 64 + (q & 63)]; }
    const float* x = g_xa + (size_t)r * 64;
    float partial = x[lane] * hw[sc * 64 + lane] + x[lane + 32] * hw[sc * 64 + lane + 32];
    partial = warpSum(partial);
    if (lane == 0) {
        float z = partial + hb[sc];
        out[6 + r] = 1.f / (1.f + expf(-z));
        float l = fmaxf(z, 0.f) - z * (float)tgt + log1pf(expf(-fabsf(z)));
        if (tgt > 0) { atomicAdd(&g_bce[sc * 4 + 0], l); atomicAdd(&g_bce[sc * 4 + 2], 1.f); }
        else         { atomicAdd(&g_bce[sc * 4 + 1], l); atomicAdd(&g_bce[sc * 4 + 3], 1.f); }
    }
}

// --------------------------- k11: finalize losses ----------------------------
__global__ void k_final(float* __restrict__ out) {
    int sc = threadIdx.x;
    if (sc < 3) {
        float np = fmaxf(g_bce[sc * 4 + 2], 1.f);
        float nn = fmaxf(g_bce[sc * 4 + 3], 1.f);
        out[sc * 2 + 0] = g_bce[sc * 4 + 0] / np;
        out[sc * 2 + 1] = g_bce[sc * 4 + 1] / nn;
    }
}

// ---------------------------------------------------------------------------
extern "C" void kernel_launch(void* const* d_in, const int* in_sizes, int n_in,
                              void* d_out, int out_size) {
    const float* image      = (const float*)d_in[0];
    const float* bn_gamma   = (const float*)d_in[1];
    const float* bn_beta    = (const float*)d_in[2];
    const int*   ht_idx     = (const int*)  d_in[3];
    const float* ht_w       = (const float*)d_in[4];
    const float* w_htconv   = (const float*)d_in[5];
    const float* htbn_gamma = (const float*)d_in[6];
    const float* htbn_beta  = (const float*)d_in[7];
    const int*   sph_idx    = (const int*)  d_in[8];
    const float* sph_w      = (const float*)d_in[9];
    const float* w_sc       = (const float*)d_in[10];
    const float* b_sc       = (const float*)d_in[11];
    const float* scbn_gamma = (const float*)d_in[12];
    const float* scbn_beta  = (const float*)d_in[13];
    const float* dgcn_w     = (const float*)d_in[14];
    const float* dgcn_b     = (const float*)d_in[15];
    const float* dgcn_hw    = (const float*)d_in[16];
    const float* dgcn_hb    = (const float*)d_in[17];
    const int*   ind0       = (const int*)  d_in[18];
    const int*   ind1       = (const int*)  d_in[19];
    const int*   ind2       = (const int*)  d_in[20];
    const int*   edge0      = (const int*)  d_in[21];
    const int*   edge1      = (const int*)  d_in[22];
    const int*   edge2      = (const int*)  d_in[23];
    const int*   target0    = (const int*)  d_in[24];
    const int*   target1    = (const int*)  d_in[25];
    const int*   target2    = (const int*)  d_in[26];
    float* out = (float*)d_out;

    cudaFuncSetAttribute(k_conv, cudaFuncAttributeMaxDynamicSharedMemorySize,
                         SMEM_CONV);

    k_zero<<<1, 512>>>();
    k_img_stats<<<kC, 256>>>(image);
    k_bnt<<<dim3(kNPIX / 32, kC / 32, kB), dim3(32, 8)>>>(image, bn_gamma, bn_beta);
    k_hough<<<(kB * kNBINS) / 8, 256>>>(ht_idx, ht_w);
    k_wprep<<<(9 * 16384 + 255) / 256, 256>>>(w_htconv);
    k_conv<<<dim3(3, kHTH / 2, kB), 256, SMEM_CONV>>>();
    k_htstats<<<510, 128>>>();
    k_sphere<<<kNR / 8, 256>>>(htbn_gamma, htbn_beta, sph_idx, sph_w,
                               ind0, ind1, ind2);
    k_sconv<<<62, 128>>>(w_sc, b_sc);
    k_scbn<<<(kNR * 64 + 255) / 256, 256>>>(scbn_gamma, scbn_beta);

    float* xa; float* xb;
    cudaGetSymbolAddress((void**)&xa, g_xa);
    cudaGetSymbolAddress((void**)&xb, g_xb);
    float* pin = xa; float* pout = xb;
    for (int layer = 0; layer < 4; layer++) {
        k_dgcn_gemm<<<kNR / 16, 128>>>(pin, dgcn_w, dgcn_b, layer);
        k_edge<<<kNR / 8, 256>>>(pout, edge0, edge1, edge2);
        float* tmp = pin; pin = pout; pout = tmp;
    }

    k_head<<<(kNR + 7) / 8, 256>>>(dgcn_hw, dgcn_hb, target0, target1, target2, out);
    k_final<<<1, 32>>>(out);
}

// round 14
// speedup vs baseline: 3.6470x; 1.0777x over previous
#include <cuda_runtime.h>
#include <cuda_bf16.h>
#include <math.h>
#include <stdint.h>

// ---------------------------------------------------------------------------
// VanishingNet full pipeline. R14: mma.sync bf16 hi/lo conv with cp.async
// double-buffered B chunks + ht-BN stats fused into conv epilogue.
// ---------------------------------------------------------------------------

#define kB     2
#define kC     128
#define kNPIX  16384
#define kHTH   184
#define kHTW   180
#define kNBINS (kHTH * kHTW)   /* 33120 */
#define kSN    1984
#define kNR    (kB * kSN)      /* 3968 */
#define kEPS   1e-5f

// --------------------------- scratch (device globals) ----------------------
__device__ float g_xT [kB * kNPIX * kC];
__device__ float g_ht [kB * kNBINS * kC];
__device__ float g_hc [kB * kNBINS * kC];
__device__ float g_sph[kNR * kC];
__device__ float g_y  [kNR * 64];
__device__ float g_xa [kNR * 64];
__device__ float g_xb [kNR * 64];
__device__ float g_uv [kNR * 128];
__device__ float g_simg[2 * kC];
__device__ float g_sht [2 * kC];
__device__ float g_ssc [2 * 192];
__device__ float g_bce [12];
// pre-swizzled bf16 weight chunks: 18 x 32KB = [tap][hi|lo], layout [co][ci]
__device__ __align__(16) unsigned char g_wB[9 * 65536];

__device__ __forceinline__ float warpSum(float v) {
    #pragma unroll
    for (int o = 16; o > 0; o >>= 1) v += __shfl_down_sync(0xffffffffu, v, o);
    return v;
}
__device__ __forceinline__ uint32_t smem_u32(const void* p) {
    uint32_t a;
    asm("{ .reg .u64 t; cvta.to.shared.u64 t, %1; cvt.u32.u64 %0, t; }"
        : "=r"(a) : "l"(p));
    return a;
}
__device__ __forceinline__ void ldsm4(uint32_t* r, uint32_t addr) {
    asm volatile("ldmatrix.sync.aligned.m8n8.x4.shared.b16 {%0,%1,%2,%3}, [%4];"
                 : "=r"(r[0]), "=r"(r[1]), "=r"(r[2]), "=r"(r[3]) : "r"(addr));
}
__device__ __forceinline__ void mma16816(float* d, const uint32_t* a,
                                         const uint32_t* b) {
    asm volatile(
        "mma.sync.aligned.m16n8k16.row.col.f32.bf16.bf16.f32 "
        "{%0,%1,%2,%3}, {%4,%5,%6,%7}, {%8,%9}, {%0,%1,%2,%3};"
        : "+f"(d[0]), "+f"(d[1]), "+f"(d[2]), "+f"(d[3])
        : "r"(a[0]), "r"(a[1]), "r"(a[2]), "r"(a[3]), "r"(b[0]), "r"(b[1]));
}
__device__ __forceinline__ void cpasync16(uint32_t dst, const void* src) {
    asm volatile("cp.async.cg.shared.global [%0], [%1], 16;"
                 :: "r"(dst), "l"(src));
}

// --------------------------- k0: zero accumulators --------------------------
__global__ void k_zero() {
    int t = threadIdx.x;
    if (t < 2 * kC) { g_sht[t] = 0.f; }
    if (t < 384)    { g_ssc[t] = 0.f; }
    if (t < 12)     { g_bce[t] = 0.f; }
}

// --------------------------- k1: image BN stats ------------------------------
__global__ __launch_bounds__(256) void k_img_stats(const float* __restrict__ img) {
    int c = blockIdx.x, t = threadIdx.x;
    float s = 0.f, s2 = 0.f;
    for (int b = 0; b < kB; b++) {
        const float* p = img + (size_t)(b * kC + c) * kNPIX;
        for (int i = t; i < kNPIX; i += 256) { float v = p[i]; s += v; s2 += v * v; }
    }
    __shared__ float rs[8], rs2[8];
    int lane = t & 31, w = t >> 5;
    s = warpSum(s); s2 = warpSum(s2);
    if (lane == 0) { rs[w] = s; rs2[w] = s2; }
    __syncthreads();
    if (t == 0) {
        float a = 0.f, a2 = 0.f;
        #pragma unroll
        for (int i = 0; i < 8; i++) { a += rs[i]; a2 += rs2[i]; }
        g_simg[c] = a; g_simg[kC + c] = a2;
    }
}

// ---------------- k2: BN + ReLU + transpose to pixel-major -------------------
__global__ void k_bnt(const float* __restrict__ img, const float* __restrict__ gam,
                      const float* __restrict__ bet) {
    __shared__ float tile[32][33];
    int p0 = blockIdx.x * 32, c0 = blockIdx.y * 32, b = blockIdx.z;
    int tx = threadIdx.x, ty = threadIdx.y;
    #pragma unroll
    for (int i = 0; i < 4; i++) {
        int c = c0 + ty * 4 + i;
        tile[ty * 4 + i][tx] = img[(size_t)(b * kC + c) * kNPIX + p0 + tx];
    }
    __syncthreads();
    int c = c0 + tx;
    float mean = g_simg[c] * (1.f / 32768.f);
    float var  = g_simg[kC + c] * (1.f / 32768.f) - mean * mean;
    float sc = gam[c] * rsqrtf(var + kEPS);
    float bi = bet[c] - mean * sc;
    #pragma unroll
    for (int i = 0; i < 4; i++) {
        int p = p0 + ty * 4 + i;
        float v = tile[tx][ty * 4 + i];
        g_xT[(size_t)(b * kNPIX + p) * kC + c] = fmaxf(sc * v + bi, 0.f);
    }
}

// --------------------------- k3: Hough voting (warp per bin) -----------------
__global__ __launch_bounds__(256) void k_hough(const int* __restrict__ hidx,
                                               const float* __restrict__ hw) {
    int gw = blockIdx.x * 8 + (threadIdx.x >> 5);
    int lane = threadIdx.x & 31;
    int b = gw / kNBINS, bin = gw - b * kNBINS;
    int   iv = 0; float wv = 0.f;
    if (lane < 8) { iv = hidx[bin * 8 + lane]; wv = hw[bin * 8 + lane]; }
    const float4* xb = (const float4*)(g_xT + (size_t)b * kNPIX * kC);
    float4 acc = make_float4(0.f, 0.f, 0.f, 0.f);
    #pragma unroll
    for (int k = 0; k < 8; k++) {
        int   ik = __shfl_sync(0xffffffffu, iv, k);
        float wk = __shfl_sync(0xffffffffu, wv, k);
        float4 v = xb[(size_t)ik * 32 + lane];
        acc.x += wk * v.x; acc.y += wk * v.y; acc.z += wk * v.z; acc.w += wk * v.w;
    }
    ((float4*)g_ht)[(size_t)(b * kNBINS + bin) * 32 + lane] = acc;
}

// ------------- k_wprep: weights -> pre-swizzled bf16 hi/lo B chunks ----------
__global__ void k_wprep(const float* __restrict__ W) {
    int i = blockIdx.x * 256 + threadIdx.x;
    if (i >= 9 * 16384) return;
    int tap = i >> 14, rem = i & 16383;
    int ci = rem >> 7, co = rem & 127;
    float w = W[((size_t)tap * 128 + ci) * 128 + co];
    __nv_bfloat16 hi = __float2bfloat16(w);
    __nv_bfloat16 lo = __float2bfloat16(w - __bfloat162float(hi));
    int off = co * 256 + (((ci >> 3) ^ (co & 7)) << 4) + (ci & 7) * 2;
    *(__nv_bfloat16*)(g_wB + (size_t)tap * 65536 + off)         = hi;
    *(__nv_bfloat16*)(g_wB + (size_t)tap * 65536 + 32768 + off) = lo;
}

// --------------------------- k4: mma.sync conv, cp.async pipelined -----------
// CTA tile: M=128 px (2y x 64x) x N=128 cout, 8 warps = 4M x 2N.
// A patch [4y][66x][128ci] hi/lo built once. 18 B chunks (tap x {hi,lo}),
// double-buffered via cp.async. Fused ht-BN stats epilogue.
#define PATCH_B   67584              /* 264 rows * 256 B */
#define SM_ALO    PATCH_B
#define SM_B      (2 * PATCH_B)      /* 135168 */
#define SMEM_CONV (SM_B + 65536)     /* 200704 */
__global__ __launch_bounds__(256, 1) void k_conv() {
    extern __shared__ __align__(16) char smem[];
    const uint32_t sA = smem_u32(smem);
    const int t    = threadIdx.x;
    const int wid  = t >> 5;
    const int lane = t & 31;
    const int x0   = blockIdx.x * 64;
    const int y0   = blockIdx.y * 2;
    const int b    = blockIdx.z;
    const int warpM = wid & 3;
    const int warpN = wid >> 2;

    // ---- prologue: issue chunk 0 into buf0 ----
    {
        uint32_t dst = sA + SM_B + t * 16;
        const char* src = (const char*)g_wB + t * 16;
        #pragma unroll
        for (int i = 0; i < 8; i++) cpasync16(dst + i * 4096, src + i * 4096);
        asm volatile("cp.async.commit_group;");
    }

    // ---- build A patch (hi/lo split, swizzled) ----
    for (int i = t; i < 264 * 16; i += 256) {
        int row = i >> 4, ch = i & 15;
        int yy = row / 66, xx = row - yy * 66;
        int gy = y0 + yy - 1, gx = x0 + xx - 1;
        bool valid = ((unsigned)gy < kHTH) && ((unsigned)gx < kHTW);
        float4 v0 = make_float4(0.f, 0.f, 0.f, 0.f), v1 = v0;
        if (valid) {
            const float4* src = (const float4*)
                (g_ht + ((size_t)(b * kNBINS + gy * kHTW + gx) * kC + ch * 8));
            v0 = src[0]; v1 = src[1];
        }
        __nv_bfloat16 h[8], l[8];
        float f[8] = {v0.x, v0.y, v0.z, v0.w, v1.x, v1.y, v1.z, v1.w};
        #pragma unroll
        for (int j = 0; j < 8; j++) {
            h[j] = __float2bfloat16(f[j]);
            l[j] = __float2bfloat16(f[j] - __bfloat162float(h[j]));
        }
        int off = row * 256 + ((ch ^ (row & 7)) << 4);
        *(uint4*)(smem + off)          = *(uint4*)h;
        *(uint4*)(smem + SM_ALO + off) = *(uint4*)l;
    }

    float acc[2][8][4];
    #pragma unroll
    for (int mi = 0; mi < 2; mi++)
        #pragma unroll
        for (int nf = 0; nf < 8; nf++)
            #pragma unroll
            for (int j = 0; j < 4; j++) acc[mi][nf][j] = 0.f;

    const int browA  = warpN * 64 + (lane & 7) + ((lane >> 4) << 3);
    const int bxor   = lane & 7;           // browA & 7
    const int bchsel = (lane >> 3) & 1;
    const int asel   = lane >> 4;

    __syncthreads();   // A patch visible to all warps

    #pragma unroll 1
    for (int j = 0; j < 18; j++) {
        const int tap = j >> 1, half = j & 1;
        const int kh = tap / 3, kw = tap - kh * 3;
        const uint32_t sBbuf = sA + SM_B + (j & 1) * 32768;
        // issue next chunk, then wait for current
        if (j + 1 < 18) {
            uint32_t dst = sA + SM_B + ((j + 1) & 1) * 32768 + t * 16;
            const char* src = (const char*)g_wB + (size_t)(j + 1) * 32768 + t * 16;
            #pragma unroll
            for (int i = 0; i < 8; i++) cpasync16(dst + i * 4096, src + i * 4096);
            asm volatile("cp.async.commit_group;");
            asm volatile("cp.async.wait_group 1;");
        } else {
            asm volatile("cp.async.wait_group 0;");
        }
        __syncthreads();   // chunk j visible; buf[(j+1)&1] writers done w/ j-1

        // A row bases for this tap
        uint32_t rbase[2]; int rx[2];
        #pragma unroll
        for (int mi = 0; mi < 2; mi++) {
            int m = warpM * 32 + mi * 16 + (lane & 15);
            int row = ((m >> 6) + kh) * 66 + (m & 63) + kw;
            rbase[mi] = sA + row * 256;
            rx[mi] = row & 7;
        }

        if (half == 0) {
            // B_hi: products hi*hi and lo*hi
            #pragma unroll 1
            for (int s = 0; s < 8; s++) {
                uint32_t ah[2][4], al[2][4];
                #pragma unroll
                for (int mi = 0; mi < 2; mi++) {
                    uint32_t ad = rbase[mi] + ((((s << 1) + asel) ^ rx[mi]) << 4);
                    ldsm4(ah[mi], ad);
                    ldsm4(al[mi], ad + SM_ALO);
                }
                #pragma unroll
                for (int np = 0; np < 4; np++) {
                    uint32_t bd = sBbuf + (browA + np * 16) * 256
                                + ((((s << 1) + bchsel) ^ bxor) << 4);
                    uint32_t bh[4];
                    ldsm4(bh, bd);
                    #pragma unroll
                    for (int mi = 0; mi < 2; mi++) {
                        mma16816(acc[mi][np * 2],     ah[mi], bh);
                        mma16816(acc[mi][np * 2 + 1], ah[mi], bh + 2);
                        mma16816(acc[mi][np * 2],     al[mi], bh);
                        mma16816(acc[mi][np * 2 + 1], al[mi], bh + 2);
                    }
                }
            }
        } else {
            // B_lo: product hi*lo
            #pragma unroll 1
            for (int s = 0; s < 8; s++) {
                uint32_t ah[2][4];
                #pragma unroll
                for (int mi = 0; mi < 2; mi++) {
                    uint32_t ad = rbase[mi] + ((((s << 1) + asel) ^ rx[mi]) << 4);
                    ldsm4(ah[mi], ad);
                }
                #pragma unroll
                for (int np = 0; np < 4; np++) {
                    uint32_t bd = sBbuf + (browA + np * 16) * 256
                                + ((((s << 1) + bchsel) ^ bxor) << 4);
                    uint32_t bl[4];
                    ldsm4(bl, bd);
                    #pragma unroll
                    for (int mi = 0; mi < 2; mi++) {
                        mma16816(acc[mi][np * 2],     ah[mi], bl);
                        mma16816(acc[mi][np * 2 + 1], ah[mi], bl + 2);
                    }
                }
            }
        }
        __syncthreads();   // compute done before next iter's cp.async overwrite
    }

    // ---- epilogue: store + fused ht-BN stats ----
    float ls1[16], ls2[16];
    #pragma unroll
    for (int i = 0; i < 16; i++) { ls1[i] = 0.f; ls2[i] = 0.f; }
    #pragma unroll
    for (int mi = 0; mi < 2; mi++) {
        #pragma unroll
        for (int nf = 0; nf < 8; nf++) {
            int n = warpN * 64 + nf * 8 + (lane & 3) * 2;
            int m = warpM * 32 + mi * 16 + (lane >> 2);
            #pragma unroll
            for (int hh = 0; hh < 2; hh++) {
                int px = m + hh * 8;
                int gx = x0 + (px & 63);
                int gy = y0 + (px >> 6);
                if (gx < kHTW) {
                    float v0 = acc[mi][nf][hh * 2];
                    float v1 = acc[mi][nf][hh * 2 + 1];
                    *(float2*)(&g_hc[(size_t)(b * kNBINS + gy * kHTW + gx) * kC + n])
                        = make_float2(v0, v1);
                    ls1[nf * 2]     += v0; ls2[nf * 2]     += v0 * v0;
                    ls1[nf * 2 + 1] += v1; ls2[nf * 2 + 1] += v1 * v1;
                }
            }
        }
    }
    __syncthreads();
    float* sS = (float*)(smem + SM_B);   // 2 x 128ch x 32 contributors
    int contrib = warpM * 8 + (lane >> 2);
    #pragma unroll
    for (int nf = 0; nf < 8; nf++) {
        #pragma unroll
        for (int cb = 0; cb < 2; cb++) {
            int ch = warpN * 64 + nf * 8 + (lane & 3) * 2 + cb;
            sS[ch * 32 + contrib]        = ls1[nf * 2 + cb];
            sS[4096 + ch * 32 + contrib] = ls2[nf * 2 + cb];
        }
    }
    __syncthreads();
    if (t < 128) {
        float a = 0.f, a2 = 0.f;
        #pragma unroll 8
        for (int i = 0; i < 32; i++) {
            a  += sS[t * 32 + i];
            a2 += sS[4096 + t * 32 + i];
        }
        atomicAdd(&g_sht[t], a);
        atomicAdd(&g_sht[kC + t], a2);
    }
}

// ---------------- k6: sphere gather (warp per node, fused ht BN+ReLU) --------
__global__ __launch_bounds__(256) void k_sphere(const float* __restrict__ gam,
                                                const float* __restrict__ bet,
                                                const int* __restrict__ sph_idx,
                                                const float* __restrict__ sph_w,
                                                const int* __restrict__ ind0,
                                                const int* __restrict__ ind1,
                                                const int* __restrict__ ind2) {
    int gw = blockIdx.x * 8 + (threadIdx.x >> 5);
    int lane = threadIdx.x & 31;
    int b = gw / kSN, s = gw - b * kSN;
    int sp;
    if (s < 1024)      sp = ind0[b * 1024 + s];
    else if (s < 1792) sp = ind1[b * 768 + (s - 1024)];
    else               sp = ind2[b * 192 + (s - 1792)];
    int   iv = 0; float wv = 0.f;
    if (lane < 16) { iv = sph_idx[sp * 16 + lane]; wv = sph_w[sp * 16 + lane]; }
    const float inv = 1.f / (float)(kB * kNBINS);
    float4 s1 = ((const float4*)g_sht)[lane];
    float4 s2 = ((const float4*)g_sht)[32 + lane];
    float4 g4 = ((const float4*)gam)[lane];
    float4 b4 = ((const float4*)bet)[lane];
    float4 sc4, bi4;
    {
        float m, v;
        m = s1.x * inv; v = s2.x * inv - m * m; sc4.x = g4.x * rsqrtf(v + kEPS); bi4.x = b4.x - m * sc4.x;
        m = s1.y * inv; v = s2.y * inv - m * m; sc4.y = g4.y * rsqrtf(v + kEPS); bi4.y = b4.y - m * sc4.y;
        m = s1.z * inv; v = s2.z * inv - m * m; sc4.z = g4.z * rsqrtf(v + kEPS); bi4.z = b4.z - m * sc4.z;
        m = s1.w * inv; v = s2.w * inv - m * m; sc4.w = g4.w * rsqrtf(v + kEPS); bi4.w = b4.w - m * sc4.w;
    }
    const float4* base = (const float4*)(g_hc + (size_t)b * kNBINS * kC);
    float4 acc = make_float4(0.f, 0.f, 0.f, 0.f);
    #pragma unroll
    for (int k = 0; k < 16; k++) {
        int   ik = __shfl_sync(0xffffffffu, iv, k);
        float wk = __shfl_sync(0xffffffffu, wv, k);
        float4 v = base[(size_t)ik * 32 + lane];
        acc.x += wk * fmaxf(sc4.x * v.x + bi4.x, 0.f);
        acc.y += wk * fmaxf(sc4.y * v.y + bi4.y, 0.f);
        acc.z += wk * fmaxf(sc4.z * v.z + bi4.z, 0.f);
        acc.w += wk * fmaxf(sc4.w * v.w + bi4.w, 0.f);
    }
    ((float4*)g_sph)[(size_t)(b * kSN + s) * 32 + lane] = acc;
}

// --------------------------- k7: sconv (1x1 conv) + stats --------------------
__global__ __launch_bounds__(128) void k_sconv(const float* __restrict__ w_sc,
                                               const float* __restrict__ b_sc) {
    __shared__ float sWt[128 * 64];
    __shared__ float sRow[2][128];
    int bx = blockIdx.x;
    int b = bx / 31, u = bx % 31;
    int sc, rbase;
    if (u < 16)      { sc = 0; rbase = b * kSN + u * 64; }
    else if (u < 28) { sc = 1; rbase = b * kSN + 1024 + (u - 16) * 64; }
    else             { sc = 2; rbase = b * kSN + 1792 + (u - 28) * 64; }
    int t = threadIdx.x, o = t & 63, half = t >> 6;
    for (int i = t; i < 8192; i += 128) {
        int c = i >> 6, oo = i & 63;
        sWt[i] = w_sc[(size_t)(sc * 64 + oo) * 128 + c];
    }
    __syncthreads();
    float bo = b_sc[sc * 64 + o];
    float ls = 0.f, ls2 = 0.f;
    for (int r0 = 0; r0 < 64; r0 += 2) {
        __syncthreads();
        sRow[0][t] = g_sph[(size_t)(rbase + r0) * 128 + t];
        sRow[1][t] = g_sph[(size_t)(rbase + r0 + 1) * 128 + t];
        __syncthreads();
        const float* rp = sRow[half];
        float acc = bo;
        #pragma unroll 8
        for (int c = 0; c < 128; c++) acc += rp[c] * sWt[c * 64 + o];
        g_y[(size_t)(rbase + r0 + half) * 64 + o] = acc;
        ls += acc; ls2 += acc * acc;
    }
    atomicAdd(&g_ssc[sc * 64 + o], ls);
    atomicAdd(&g_ssc[192 + sc * 64 + o], ls2);
}

// --------------------------- k8: sconv BN + ReLU -----------------------------
__global__ void k_scbn(const float* __restrict__ gam, const float* __restrict__ bet) {
    int idx = blockIdx.x * blockDim.x + threadIdx.x;
    if (idx >= kNR * 64) return;
    int r = idx >> 6, o = idx & 63;
    int s = r % kSN;
    int sc = (s < 1024) ? 0 : (s < 1792 ? 1 : 2);
    float cnt = (sc == 0) ? 2048.f : (sc == 1 ? 1536.f : 384.f);
    float mean = g_ssc[sc * 64 + o] / cnt;
    float var  = g_ssc[192 + sc * 64 + o] / cnt - mean * mean;
    float scv = gam[sc * 64 + o] * rsqrtf(var + kEPS);
    float bi  = bet[sc * 64 + o] - mean * scv;
    g_xa[idx] = fmaxf(scv * g_y[idx] + bi, 0.f);
}

// ------------------- k9a: dgcn per-layer GEMM: [U | V] -----------------------
__global__ __launch_bounds__(128) void k_dgcn_gemm(const float* __restrict__ xin,
                                                   const float* __restrict__ dgw,
                                                   const float* __restrict__ dgb,
                                                   int layer) {
    __shared__ __align__(16) float sWc[64 * 128];
    __shared__ __align__(16) float sX[16 * 64];
    int t = threadIdx.x;
    int r0 = blockIdx.x * 16;
    int b = r0 / kSN, s = r0 - b * kSN;
    int sc = (s < 1024) ? 0 : (s < 1792 ? 1 : 2);
    const float* W  = dgw + (size_t)(sc * 4 + layer) * 8192;
    const float* bi = dgb + (size_t)(sc * 4 + layer) * 64;
    for (int i = t; i < 4096; i += 128) {
        int c = i >> 6, o = i & 63;
        float w2 = W[4096 + i];
        sWc[c * 128 + o]      = W[i] - w2;
        sWc[c * 128 + 64 + o] = w2;
    }
    for (int i = t; i < 1024; i += 128) sX[i] = xin[(size_t)r0 * 64 + i];
    __syncthreads();
    float acc[16];
    float binit = (t < 64) ? bi[t] : 0.f;
    #pragma unroll
    for (int rr = 0; rr < 16; rr++) acc[rr] = binit;
    #pragma unroll 4
    for (int c4 = 0; c4 < 16; c4++) {
        float w0 = sWc[(c4 * 4 + 0) * 128 + t];
        float w1 = sWc[(c4 * 4 + 1) * 128 + t];
        float w2 = sWc[(c4 * 4 + 2) * 128 + t];
        float w3 = sWc[(c4 * 4 + 3) * 128 + t];
        #pragma unroll
        for (int rr = 0; rr < 16; rr++) {
            float4 xv = *reinterpret_cast<const float4*>(&sX[rr * 64 + c4 * 4]);
            acc[rr] += xv.x * w0 + xv.y * w1 + xv.z * w2 + xv.w * w3;
        }
    }
    #pragma unroll
    for (int rr = 0; rr < 16; rr++)
        g_uv[(size_t)(r0 + rr) * 128 + t] = acc[rr];
}

// ------------------- k9b: dgcn edge phase: max_k relu(U_c + V_n) -------------
__global__ __launch_bounds__(256) void k_edge(float* __restrict__ xout,
                                              const int* __restrict__ e0,
                                              const int* __restrict__ e1,
                                              const int* __restrict__ e2) {
    int r = blockIdx.x * 8 + (threadIdx.x >> 5);
    int lane = threadIdx.x & 31;
    int b = r / kSN, s = r - b * kSN;
    int rbase, enBase;
    const int* E;
    if (s < 1024) {
        rbase = b * kSN;
        E = e0; enBase = b * 2 * 8192 + 8192 + s * 8;
    } else if (s < 1792) {
        int q = s - 1024, v = q >> 8, j = q & 255, g = b * 3 + v;
        rbase = b * kSN + 1024 + v * 256;
        E = e1; enBase = g * 2 * 2048 + 2048 + j * 8;
    } else {
        int q = s - 1792, v = q >> 6, j = q & 63, g = b * 3 + v;
        rbase = b * kSN + 1792 + v * 64;
        E = e2; enBase = g * 2 * 512 + 512 + j * 8;
    }
    int nv = (lane < 8) ? E[enBase + lane] : 0;
    float u0 = g_uv[(size_t)r * 128 + lane];
    float u1 = g_uv[(size_t)r * 128 + 32 + lane];
    float m0 = 0.f, m1 = 0.f;
    #pragma unroll
    for (int k = 0; k < 8; k++) {
        int n = rbase + __shfl_sync(0xffffffffu, nv, k);
        float v0 = g_uv[(size_t)n * 128 + 64 + lane];
        float v1 = g_uv[(size_t)n * 128 + 96 + lane];
        m0 = fmaxf(m0, u0 + v0);
        m1 = fmaxf(m1, u1 + v1);
    }
    xout[(size_t)r * 64 + lane]      = m0;
    xout[(size_t)r * 64 + 32 + lane] = m1;
}

// --------------------------- k10: head + BCE accumulation --------------------
__global__ __launch_bounds__(256) void k_head(const float* __restrict__ hw,
                                              const float* __restrict__ hb,
                                              const int* __restrict__ t0,
                                              const int* __restrict__ t1,
                                              const int* __restrict__ t2,
                                              float* __restrict__ out) {
    int t = threadIdx.x;
    int warp = t >> 5, lane = t & 31;
    int r = blockIdx.x * 8 + warp;
    if (r >= kNR) return;
    int b = r / kSN, s = r - b * kSN;
    int sc, tgt;
    if (s < 1024)      { sc = 0; tgt = t0[b * 1024 + s]; }
    else if (s < 1792) { sc = 1; int q = s - 1024; tgt = t1[(b * 3 + (q >> 8)) * 256 + (q & 255)]; }
    else               { sc = 2; int q = s - 1792; tgt = t2[(b * 3 + (q >> 6)) * 64 + (q & 63)]; }
    const float* x = g_xa + (size_t)r * 64;
    float partial = x[lane] * hw[sc * 64 + lane] + x[lane + 32] * hw[sc * 64 + lane + 32];
    partial = warpSum(partial);
    if (lane == 0) {
        float z = partial + hb[sc];
        out[6 + r] = 1.f / (1.f + expf(-z));
        float l = fmaxf(z, 0.f) - z * (float)tgt + log1pf(expf(-fabsf(z)));
        if (tgt > 0) { atomicAdd(&g_bce[sc * 4 + 0], l); atomicAdd(&g_bce[sc * 4 + 2], 1.f); }
        else         { atomicAdd(&g_bce[sc * 4 + 1], l); atomicAdd(&g_bce[sc * 4 + 3], 1.f); }
    }
}

// --------------------------- k11: finalize losses ----------------------------
__global__ void k_final(float* __restrict__ out) {
    int sc = threadIdx.x;
    if (sc < 3) {
        float np = fmaxf(g_bce[sc * 4 + 2], 1.f);
        float nn = fmaxf(g_bce[sc * 4 + 3], 1.f);
        out[sc * 2 + 0] = g_bce[sc * 4 + 0] / np;
        out[sc * 2 + 1] = g_bce[sc * 4 + 1] / nn;
    }
}

// ---------------------------------------------------------------------------
extern "C" void kernel_launch(void* const* d_in, const int* in_sizes, int n_in,
                              void* d_out, int out_size) {
    const float* image      = (const float*)d_in[0];
    const float* bn_gamma   = (const float*)d_in[1];
    const float* bn_beta    = (const float*)d_in[2];
    const int*   ht_idx     = (const int*)  d_in[3];
    const float* ht_w       = (const float*)d_in[4];
    const float* w_htconv   = (const float*)d_in[5];
    const float* htbn_gamma = (const float*)d_in[6];
    const float* htbn_beta  = (const float*)d_in[7];
    const int*   sph_idx    = (const int*)  d_in[8];
    const float* sph_w      = (const float*)d_in[9];
    const float* w_sc       = (const float*)d_in[10];
    const float* b_sc       = (const float*)d_in[11];
    const float* scbn_gamma = (const float*)d_in[12];
    const float* scbn_beta  = (const float*)d_in[13];
    const float* dgcn_w     = (const float*)d_in[14];
    const float* dgcn_b     = (const float*)d_in[15];
    const float* dgcn_hw    = (const float*)d_in[16];
    const float* dgcn_hb    = (const float*)d_in[17];
    const int*   ind0       = (const int*)  d_in[18];
    const int*   ind1       = (const int*)  d_in[19];
    const int*   ind2       = (const int*)  d_in[20];
    const int*   edge0      = (const int*)  d_in[21];
    const int*   edge1      = (const int*)  d_in[22];
    const int*   edge2      = (const int*)  d_in[23];
    const int*   target0    = (const int*)  d_in[24];
    const int*   target1    = (const int*)  d_in[25];
    const int*   target2    = (const int*)  d_in[26];
    float* out = (float*)d_out;

    cudaFuncSetAttribute(k_conv, cudaFuncAttributeMaxDynamicSharedMemorySize,
                         SMEM_CONV);

    k_zero<<<1, 512>>>();
    k_img_stats<<<kC, 256>>>(image);
    k_bnt<<<dim3(kNPIX / 32, kC / 32, kB), dim3(32, 8)>>>(image, bn_gamma, bn_beta);
    k_hough<<<(kB * kNBINS) / 8, 256>>>(ht_idx, ht_w);
    k_wprep<<<(9 * 16384 + 255) / 256, 256>>>(w_htconv);
    k_conv<<<dim3(3, kHTH / 2, kB), 256, SMEM_CONV>>>();
    k_sphere<<<kNR / 8, 256>>>(htbn_gamma, htbn_beta, sph_idx, sph_w,
                               ind0, ind1, ind2);
    k_sconv<<<62, 128>>>(w_sc, b_sc);
    k_scbn<<<(kNR * 64 + 255) / 256, 256>>>(scbn_gamma, scbn_beta);

    float* xa; float* xb;
    cudaGetSymbolAddress((void**)&xa, g_xa);
    cudaGetSymbolAddress((void**)&xb, g_xb);
    float* pin = xa; float* pout = xb;
    for (int layer = 0; layer < 4; layer++) {
        k_dgcn_gemm<<<kNR / 16, 128>>>(pin, dgcn_w, dgcn_b, layer);
        k_edge<<<kNR / 8, 256>>>(pout, edge0, edge1, edge2);
        float* tmp = pin; pin = pout; pout = tmp;
    }

    k_head<<<(kNR + 7) / 8, 256>>>(dgcn_hw, dgcn_hb, target0, target1, target2, out);
    k_final<<<1, 32>>>(out);
}

// round 15
// speedup vs baseline: 4.6641x; 1.2789x over previous
#include <cuda_runtime.h>
#include <cuda_fp16.h>
#include <math.h>
#include <stdint.h>

// ---------------------------------------------------------------------------
// VanishingNet full pipeline. R15: fp16 2-product mma.sync conv @ 2 CTAs/SM,
// fully fused dgcn tail (BN+gemm / edge+gemm / edge+head).
// ---------------------------------------------------------------------------

#define kB     2
#define kC     128
#define kNPIX  16384
#define kHTH   184
#define kHTW   180
#define kNBINS (kHTH * kHTW)   /* 33120 */
#define kSN    1984
#define kNR    (kB * kSN)      /* 3968 */
#define kEPS   1e-5f

// --------------------------- scratch (device globals) ----------------------
__device__ float g_xT [kB * kNPIX * kC];
__device__ float g_ht [kB * kNBINS * kC];
__device__ float g_hc [kB * kNBINS * kC];
__device__ float g_sph[kNR * kC];
__device__ float g_y  [kNR * 64];
__device__ float g_uv [kNR * 128];
__device__ float g_uv2[kNR * 128];
__device__ float g_simg[2 * kC];
__device__ float g_sht [2 * kC];
__device__ float g_ssc [2 * 192];
__device__ float g_bce [12];
// pre-swizzled fp16 weight chunks: [tap][hi 32KB | lo 32KB], layout [co][ci]
__device__ __align__(16) unsigned char g_wB[9 * 65536];

__device__ __forceinline__ float warpSum(float v) {
    #pragma unroll
    for (int o = 16; o > 0; o >>= 1) v += __shfl_down_sync(0xffffffffu, v, o);
    return v;
}
__device__ __forceinline__ uint32_t smem_u32(const void* p) {
    uint32_t a;
    asm("{ .reg .u64 t; cvta.to.shared.u64 t, %1; cvt.u32.u64 %0, t; }"
        : "=r"(a) : "l"(p));
    return a;
}
__device__ __forceinline__ void ldsm4(uint32_t* r, uint32_t addr) {
    asm volatile("ldmatrix.sync.aligned.m8n8.x4.shared.b16 {%0,%1,%2,%3}, [%4];"
                 : "=r"(r[0]), "=r"(r[1]), "=r"(r[2]), "=r"(r[3]) : "r"(addr));
}
__device__ __forceinline__ void mma16816(float* d, const uint32_t* a,
                                         const uint32_t* b) {
    asm volatile(
        "mma.sync.aligned.m16n8k16.row.col.f32.f16.f16.f32 "
        "{%0,%1,%2,%3}, {%4,%5,%6,%7}, {%8,%9}, {%0,%1,%2,%3};"
        : "+f"(d[0]), "+f"(d[1]), "+f"(d[2]), "+f"(d[3])
        : "r"(a[0]), "r"(a[1]), "r"(a[2]), "r"(a[3]), "r"(b[0]), "r"(b[1]));
}
__device__ __forceinline__ void cpasync16(uint32_t dst, const void* src) {
    asm volatile("cp.async.cg.shared.global [%0], [%1], 16;"
                 :: "r"(dst), "l"(src));
}

// --------------------------- k0: zero accumulators --------------------------
__global__ void k_zero() {
    int t = threadIdx.x;
    if (t < 2 * kC) { g_sht[t] = 0.f; }
    if (t < 384)    { g_ssc[t] = 0.f; }
    if (t < 12)     { g_bce[t] = 0.f; }
}

// --------------------------- k1: image BN stats ------------------------------
__global__ __launch_bounds__(256) void k_img_stats(const float* __restrict__ img) {
    int c = blockIdx.x, t = threadIdx.x;
    float s = 0.f, s2 = 0.f;
    for (int b = 0; b < kB; b++) {
        const float* p = img + (size_t)(b * kC + c) * kNPIX;
        for (int i = t; i < kNPIX; i += 256) { float v = p[i]; s += v; s2 += v * v; }
    }
    __shared__ float rs[8], rs2[8];
    int lane = t & 31, w = t >> 5;
    s = warpSum(s); s2 = warpSum(s2);
    if (lane == 0) { rs[w] = s; rs2[w] = s2; }
    __syncthreads();
    if (t == 0) {
        float a = 0.f, a2 = 0.f;
        #pragma unroll
        for (int i = 0; i < 8; i++) { a += rs[i]; a2 += rs2[i]; }
        g_simg[c] = a; g_simg[kC + c] = a2;
    }
}

// ---------------- k2: BN + ReLU + transpose to pixel-major -------------------
__global__ void k_bnt(const float* __restrict__ img, const float* __restrict__ gam,
                      const float* __restrict__ bet) {
    __shared__ float tile[32][33];
    int p0 = blockIdx.x * 32, c0 = blockIdx.y * 32, b = blockIdx.z;
    int tx = threadIdx.x, ty = threadIdx.y;
    #pragma unroll
    for (int i = 0; i < 4; i++) {
        int c = c0 + ty * 4 + i;
        tile[ty * 4 + i][tx] = img[(size_t)(b * kC + c) * kNPIX + p0 + tx];
    }
    __syncthreads();
    int c = c0 + tx;
    float mean = g_simg[c] * (1.f / 32768.f);
    float var  = g_simg[kC + c] * (1.f / 32768.f) - mean * mean;
    float sc = gam[c] * rsqrtf(var + kEPS);
    float bi = bet[c] - mean * sc;
    #pragma unroll
    for (int i = 0; i < 4; i++) {
        int p = p0 + ty * 4 + i;
        float v = tile[tx][ty * 4 + i];
        g_xT[(size_t)(b * kNPIX + p) * kC + c] = fmaxf(sc * v + bi, 0.f);
    }
}

// --------------------------- k3: Hough voting (warp per bin) -----------------
__global__ __launch_bounds__(256) void k_hough(const int* __restrict__ hidx,
                                               const float* __restrict__ hw) {
    int gw = blockIdx.x * 8 + (threadIdx.x >> 5);
    int lane = threadIdx.x & 31;
    int b = gw / kNBINS, bin = gw - b * kNBINS;
    int   iv = 0; float wv = 0.f;
    if (lane < 8) { iv = hidx[bin * 8 + lane]; wv = hw[bin * 8 + lane]; }
    const float4* xb = (const float4*)(g_xT + (size_t)b * kNPIX * kC);
    float4 acc = make_float4(0.f, 0.f, 0.f, 0.f);
    #pragma unroll
    for (int k = 0; k < 8; k++) {
        int   ik = __shfl_sync(0xffffffffu, iv, k);
        float wk = __shfl_sync(0xffffffffu, wv, k);
        float4 v = xb[(size_t)ik * 32 + lane];
        acc.x += wk * v.x; acc.y += wk * v.y; acc.z += wk * v.z; acc.w += wk * v.w;
    }
    ((float4*)g_ht)[(size_t)(b * kNBINS + bin) * 32 + lane] = acc;
}

// ------------- k_wprep: weights -> pre-swizzled fp16 hi/lo B chunks ----------
__global__ void k_wprep(const float* __restrict__ W) {
    int i = blockIdx.x * 256 + threadIdx.x;
    if (i >= 9 * 16384) return;
    int tap = i >> 14, rem = i & 16383;
    int ci = rem >> 7, co = rem & 127;
    float w = W[((size_t)tap * 128 + ci) * 128 + co];
    __half hi = __float2half(w);
    __half lo = __float2half(w - __half2float(hi));
    int off = co * 256 + (((ci >> 3) ^ (co & 7)) << 4) + (ci & 7) * 2;
    *(__half*)(g_wB + (size_t)tap * 65536 + off)         = hi;
    *(__half*)(g_wB + (size_t)tap * 65536 + 32768 + off) = lo;
}

// --------------------------- k4: fp16 2-product mma.sync conv ----------------
// CTA tile: M=128 px (2y x 64x) x N=128 cout, 8 warps = 4M x 2N, 2 CTAs/SM.
// A patch = fp16(x) only (66 KB). 18 B chunks (tap x {hi,lo}) single-buffered;
// every chunk contributes A*B to the same accumulators. Fused ht-BN stats.
#define PATCH_B   67584              /* 264 rows * 256 B */
#define SM_B      PATCH_B
#define SMEM_CONV (PATCH_B + 32768)  /* 100352 */
__global__ __launch_bounds__(256, 2) void k_conv() {
    extern __shared__ __align__(16) char smem[];
    const uint32_t sA = smem_u32(smem);
    const uint32_t sB = sA + SM_B;
    const int t    = threadIdx.x;
    const int wid  = t >> 5;
    const int lane = t & 31;
    const int x0   = blockIdx.x * 64;
    const int y0   = blockIdx.y * 2;
    const int b    = blockIdx.z;
    const int warpM = wid & 3;
    const int warpN = wid >> 2;

    // ---- build A patch: fp16(x), swizzled ----
    for (int i = t; i < 264 * 16; i += 256) {
        int row = i >> 4, ch = i & 15;
        int yy = row / 66, xx = row - yy * 66;
        int gy = y0 + yy - 1, gx = x0 + xx - 1;
        bool valid = ((unsigned)gy < kHTH) && ((unsigned)gx < kHTW);
        float4 v0 = make_float4(0.f, 0.f, 0.f, 0.f), v1 = v0;
        if (valid) {
            const float4* src = (const float4*)
                (g_ht + ((size_t)(b * kNBINS + gy * kHTW + gx) * kC + ch * 8));
            v0 = src[0]; v1 = src[1];
        }
        __half h[8];
        h[0] = __float2half(v0.x); h[1] = __float2half(v0.y);
        h[2] = __float2half(v0.z); h[3] = __float2half(v0.w);
        h[4] = __float2half(v1.x); h[5] = __float2half(v1.y);
        h[6] = __float2half(v1.z); h[7] = __float2half(v1.w);
        int off = row * 256 + ((ch ^ (row & 7)) << 4);
        *(uint4*)(smem + off) = *(uint4*)h;
    }

    float acc[2][8][4];
    #pragma unroll
    for (int mi = 0; mi < 2; mi++)
        #pragma unroll
        for (int nf = 0; nf < 8; nf++)
            #pragma unroll
            for (int j = 0; j < 4; j++) acc[mi][nf][j] = 0.f;

    const int browA  = warpN * 64 + (lane & 7) + ((lane >> 4) << 3);
    const int bxor   = lane & 7;
    const int bchsel = (lane >> 3) & 1;
    const int asel   = lane >> 4;

    __syncthreads();   // A patch visible

    #pragma unroll 1
    for (int j = 0; j < 18; j++) {
        const int tap = j >> 1;
        const int kh = tap / 3, kw = tap - kh * 3;
        // load chunk j (32 KB)
        {
            uint32_t dst = sB + t * 16;
            const char* src = (const char*)g_wB + (size_t)j * 32768 + t * 16;
            #pragma unroll
            for (int i = 0; i < 8; i++) cpasync16(dst + i * 4096, src + i * 4096);
            asm volatile("cp.async.commit_group;");
            asm volatile("cp.async.wait_group 0;");
        }
        __syncthreads();   // chunk visible to all warps

        uint32_t rbase2[2]; int rx[2];
        #pragma unroll
        for (int mi = 0; mi < 2; mi++) {
            int m = warpM * 32 + mi * 16 + (lane & 15);
            int row = ((m >> 6) + kh) * 66 + (m & 63) + kw;
            rbase2[mi] = sA + row * 256;
            rx[mi] = row & 7;
        }
        #pragma unroll 1
        for (int s = 0; s < 8; s++) {
            uint32_t ah[2][4];
            #pragma unroll
            for (int mi = 0; mi < 2; mi++) {
                uint32_t ad = rbase2[mi] + ((((s << 1) + asel) ^ rx[mi]) << 4);
                ldsm4(ah[mi], ad);
            }
            #pragma unroll
            for (int np = 0; np < 4; np++) {
                uint32_t bd = sB + (browA + np * 16) * 256
                            + ((((s << 1) + bchsel) ^ bxor) << 4);
                uint32_t bh[4];
                ldsm4(bh, bd);
                #pragma unroll
                for (int mi = 0; mi < 2; mi++) {
                    mma16816(acc[mi][np * 2],     ah[mi], bh);
                    mma16816(acc[mi][np * 2 + 1], ah[mi], bh + 2);
                }
            }
        }
        __syncthreads();   // compute done before next chunk overwrite
    }

    // ---- epilogue: store + fused ht-BN stats ----
    float ls1[16], ls2[16];
    #pragma unroll
    for (int i = 0; i < 16; i++) { ls1[i] = 0.f; ls2[i] = 0.f; }
    #pragma unroll
    for (int mi = 0; mi < 2; mi++) {
        #pragma unroll
        for (int nf = 0; nf < 8; nf++) {
            int n = warpN * 64 + nf * 8 + (lane & 3) * 2;
            int m = warpM * 32 + mi * 16 + (lane >> 2);
            #pragma unroll
            for (int hh = 0; hh < 2; hh++) {
                int px = m + hh * 8;
                int gx = x0 + (px & 63);
                int gy = y0 + (px >> 6);
                if (gx < kHTW) {
                    float v0 = acc[mi][nf][hh * 2];
                    float v1 = acc[mi][nf][hh * 2 + 1];
                    *(float2*)(&g_hc[(size_t)(b * kNBINS + gy * kHTW + gx) * kC + n])
                        = make_float2(v0, v1);
                    ls1[nf * 2]     += v0; ls2[nf * 2]     += v0 * v0;
                    ls1[nf * 2 + 1] += v1; ls2[nf * 2 + 1] += v1 * v1;
                }
            }
        }
    }
    __syncthreads();
    float* sS = (float*)smem;   // reuse A region: 2 x 128ch x 32 contributors
    int contrib = warpM * 8 + (lane >> 2);
    #pragma unroll
    for (int nf = 0; nf < 8; nf++) {
        #pragma unroll
        for (int cb = 0; cb < 2; cb++) {
            int ch = warpN * 64 + nf * 8 + (lane & 3) * 2 + cb;
            sS[ch * 32 + contrib]        = ls1[nf * 2 + cb];
            sS[4096 + ch * 32 + contrib] = ls2[nf * 2 + cb];
        }
    }
    __syncthreads();
    if (t < 128) {
        float a = 0.f, a2 = 0.f;
        #pragma unroll 8
        for (int i = 0; i < 32; i++) {
            a  += sS[t * 32 + i];
            a2 += sS[4096 + t * 32 + i];
        }
        atomicAdd(&g_sht[t], a);
        atomicAdd(&g_sht[kC + t], a2);
    }
}

// ---------------- k6: sphere gather (warp per node, fused ht BN+ReLU) --------
__global__ __launch_bounds__(256) void k_sphere(const float* __restrict__ gam,
                                                const float* __restrict__ bet,
                                                const int* __restrict__ sph_idx,
                                                const float* __restrict__ sph_w,
                                                const int* __restrict__ ind0,
                                                const int* __restrict__ ind1,
                                                const int* __restrict__ ind2) {
    int gw = blockIdx.x * 8 + (threadIdx.x >> 5);
    int lane = threadIdx.x & 31;
    int b = gw / kSN, s = gw - b * kSN;
    int sp;
    if (s < 1024)      sp = ind0[b * 1024 + s];
    else if (s < 1792) sp = ind1[b * 768 + (s - 1024)];
    else               sp = ind2[b * 192 + (s - 1792)];
    int   iv = 0; float wv = 0.f;
    if (lane < 16) { iv = sph_idx[sp * 16 + lane]; wv = sph_w[sp * 16 + lane]; }
    const float inv = 1.f / (float)(kB * kNBINS);
    float4 s1 = ((const float4*)g_sht)[lane];
    float4 s2 = ((const float4*)g_sht)[32 + lane];
    float4 g4 = ((const float4*)gam)[lane];
    float4 b4 = ((const float4*)bet)[lane];
    float4 sc4, bi4;
    {
        float m, v;
        m = s1.x * inv; v = s2.x * inv - m * m; sc4.x = g4.x * rsqrtf(v + kEPS); bi4.x = b4.x - m * sc4.x;
        m = s1.y * inv; v = s2.y * inv - m * m; sc4.y = g4.y * rsqrtf(v + kEPS); bi4.y = b4.y - m * sc4.y;
        m = s1.z * inv; v = s2.z * inv - m * m; sc4.z = g4.z * rsqrtf(v + kEPS); bi4.z = b4.z - m * sc4.z;
        m = s1.w * inv; v = s2.w * inv - m * m; sc4.w = g4.w * rsqrtf(v + kEPS); bi4.w = b4.w - m * sc4.w;
    }
    const float4* base = (const float4*)(g_hc + (size_t)b * kNBINS * kC);
    float4 acc = make_float4(0.f, 0.f, 0.f, 0.f);
    #pragma unroll
    for (int k = 0; k < 16; k++) {
        int   ik = __shfl_sync(0xffffffffu, iv, k);
        float wk = __shfl_sync(0xffffffffu, wv, k);
        float4 v = base[(size_t)ik * 32 + lane];
        acc.x += wk * fmaxf(sc4.x * v.x + bi4.x, 0.f);
        acc.y += wk * fmaxf(sc4.y * v.y + bi4.y, 0.f);
        acc.z += wk * fmaxf(sc4.z * v.z + bi4.z, 0.f);
        acc.w += wk * fmaxf(sc4.w * v.w + bi4.w, 0.f);
    }
    ((float4*)g_sph)[(size_t)(b * kSN + s) * 32 + lane] = acc;
}

// --------------------------- k7: sconv (1x1 conv) + stats --------------------
__global__ __launch_bounds__(128) void k_sconv(const float* __restrict__ w_sc,
                                               const float* __restrict__ b_sc) {
    __shared__ float sWt[128 * 64];
    __shared__ float sRow[2][128];
    int bx = blockIdx.x;
    int b = bx / 31, u = bx % 31;
    int sc, rbase;
    if (u < 16)      { sc = 0; rbase = b * kSN + u * 64; }
    else if (u < 28) { sc = 1; rbase = b * kSN + 1024 + (u - 16) * 64; }
    else             { sc = 2; rbase = b * kSN + 1792 + (u - 28) * 64; }
    int t = threadIdx.x, o = t & 63, half = t >> 6;
    for (int i = t; i < 8192; i += 128) {
        int c = i >> 6, oo = i & 63;
        sWt[i] = w_sc[(size_t)(sc * 64 + oo) * 128 + c];
    }
    __syncthreads();
    float bo = b_sc[sc * 64 + o];
    float ls = 0.f, ls2 = 0.f;
    for (int r0 = 0; r0 < 64; r0 += 2) {
        __syncthreads();
        sRow[0][t] = g_sph[(size_t)(rbase + r0) * 128 + t];
        sRow[1][t] = g_sph[(size_t)(rbase + r0 + 1) * 128 + t];
        __syncthreads();
        const float* rp = sRow[half];
        float acc = bo;
        #pragma unroll 8
        for (int c = 0; c < 128; c++) acc += rp[c] * sWt[c * 64 + o];
        g_y[(size_t)(rbase + r0 + half) * 64 + o] = acc;
        ls += acc; ls2 += acc * acc;
    }
    atomicAdd(&g_ssc[sc * 64 + o], ls);
    atomicAdd(&g_ssc[192 + sc * 64 + o], ls2);
}

// ---------------- dgcn fused kernels ----------------------------------------
// F0: rows r0..r0+15: x = relu(BN(g_y)) inline, GEMM layer0 -> uvout.
__global__ __launch_bounds__(128) void k_dgcn_first(const float* __restrict__ dgw,
                                                    const float* __restrict__ dgb,
                                                    const float* __restrict__ gam,
                                                    const float* __restrict__ bet,
                                                    float* __restrict__ uvout) {
    __shared__ __align__(16) float sWc[64 * 128];
    __shared__ __align__(16) float sX[16 * 64];
    int t = threadIdx.x;
    int r0 = blockIdx.x * 16;
    int b = r0 / kSN, s0 = r0 - b * kSN;
    int sc = (s0 < 1024) ? 0 : (s0 < 1792 ? 1 : 2);
    const float* W  = dgw + (size_t)(sc * 4) * 8192;
    const float* bi = dgb + (size_t)(sc * 4) * 64;
    for (int i = t; i < 4096; i += 128) {
        int c = i >> 6, o = i & 63;
        float w2 = W[4096 + i];
        sWc[c * 128 + o]      = W[i] - w2;
        sWc[c * 128 + 64 + o] = w2;
    }
    {
        int o = t & 63;
        float cnt = (sc == 0) ? 2048.f : (sc == 1 ? 1536.f : 384.f);
        float mean = g_ssc[sc * 64 + o] / cnt;
        float var  = g_ssc[192 + sc * 64 + o] / cnt - mean * mean;
        float scv = gam[sc * 64 + o] * rsqrtf(var + kEPS);
        float biv = bet[sc * 64 + o] - mean * scv;
        for (int i = t; i < 1024; i += 128)
            sX[i] = fmaxf(scv * g_y[(size_t)r0 * 64 + i] + biv, 0.f);
    }
    __syncthreads();
    float acc[16];
    float binit = (t < 64) ? bi[t] : 0.f;
    #pragma unroll
    for (int rr = 0; rr < 16; rr++) acc[rr] = binit;
    #pragma unroll 4
    for (int c4 = 0; c4 < 16; c4++) {
        float w0 = sWc[(c4 * 4 + 0) * 128 + t];
        float w1 = sWc[(c4 * 4 + 1) * 128 + t];
        float w2 = sWc[(c4 * 4 + 2) * 128 + t];
        float w3 = sWc[(c4 * 4 + 3) * 128 + t];
        #pragma unroll
        for (int rr = 0; rr < 16; rr++) {
            float4 xv = *reinterpret_cast<const float4*>(&sX[rr * 64 + c4 * 4]);
            acc[rr] += xv.x * w0 + xv.y * w1 + xv.z * w2 + xv.w * w3;
        }
    }
    #pragma unroll
    for (int rr = 0; rr < 16; rr++)
        uvout[(size_t)(r0 + rr) * 128 + t] = acc[rr];
}

// F_mid: edge from uvin -> x (16 rows), GEMM layer l -> uvout.
__global__ __launch_bounds__(128) void k_dgcn_mid(const float* __restrict__ dgw,
                                                  const float* __restrict__ dgb,
                                                  const float* __restrict__ uvin,
                                                  float* __restrict__ uvout,
                                                  const int* __restrict__ e0,
                                                  const int* __restrict__ e1,
                                                  const int* __restrict__ e2,
                                                  int layer) {
    __shared__ __align__(16) float sWc[64 * 128];
    __shared__ __align__(16) float sX[16 * 64];
    __shared__ int sNbr[128];
    int t = threadIdx.x;
    int r0 = blockIdx.x * 16;
    int b = r0 / kSN, s0 = r0 - b * kSN;
    int sc = (s0 < 1024) ? 0 : (s0 < 1792 ? 1 : 2);
    const float* W  = dgw + (size_t)(sc * 4 + layer) * 8192;
    const float* bi = dgb + (size_t)(sc * 4 + layer) * 64;
    for (int i = t; i < 4096; i += 128) {
        int c = i >> 6, o = i & 63;
        float w2 = W[4096 + i];
        sWc[c * 128 + o]      = W[i] - w2;
        sWc[c * 128 + 64 + o] = w2;
    }
    // neighbor stage: thread t -> (row t>>3, k t&7)
    {
        int r = r0 + (t >> 3);
        int bb = r / kSN, ss = r - bb * kSN;
        const int* E; int en;
        if (ss < 1024)      { E = e0; en = bb * 16384 + 8192 + ss * 8; }
        else if (ss < 1792) { int q = ss - 1024, v = q >> 8, jj = q & 255, g = bb * 3 + v;
                              E = e1; en = g * 4096 + 2048 + jj * 8; }
        else                { int q = ss - 1792, v = q >> 6, jj = q & 63, g = bb * 3 + v;
                              E = e2; en = g * 1024 + 512 + jj * 8; }
        sNbr[t] = E[en + (t & 7)];
    }
    int rbase;
    if (s0 < 1024)      rbase = b * kSN;
    else if (s0 < 1792) rbase = b * kSN + 1024 + ((s0 - 1024) >> 8) * 256;
    else                rbase = b * kSN + 1792 + ((s0 - 1792) >> 6) * 64;
    __syncthreads();
    // edge: x[rr][o] = max_k relu(U[rr][o] + V[n_k][o])
    {
        int o = t & 63, rg = t >> 6;
        #pragma unroll
        for (int rr8 = 0; rr8 < 8; rr8++) {
            int rr = rg * 8 + rr8;
            float U = uvin[(size_t)(r0 + rr) * 128 + o];
            float m = 0.f;
            #pragma unroll
            for (int k = 0; k < 8; k++) {
                int n = sNbr[rr * 8 + k];
                m = fmaxf(m, U + uvin[(size_t)(rbase + n) * 128 + 64 + o]);
            }
            sX[rr * 64 + o] = m;
        }
    }
    __syncthreads();
    float acc[16];
    float binit = (t < 64) ? bi[t] : 0.f;
    #pragma unroll
    for (int rr = 0; rr < 16; rr++) acc[rr] = binit;
    #pragma unroll 4
    for (int c4 = 0; c4 < 16; c4++) {
        float w0 = sWc[(c4 * 4 + 0) * 128 + t];
        float w1 = sWc[(c4 * 4 + 1) * 128 + t];
        float w2 = sWc[(c4 * 4 + 2) * 128 + t];
        float w3 = sWc[(c4 * 4 + 3) * 128 + t];
        #pragma unroll
        for (int rr = 0; rr < 16; rr++) {
            float4 xv = *reinterpret_cast<const float4*>(&sX[rr * 64 + c4 * 4]);
            acc[rr] += xv.x * w0 + xv.y * w1 + xv.z * w2 + xv.w * w3;
        }
    }
    #pragma unroll
    for (int rr = 0; rr < 16; rr++)
        uvout[(size_t)(r0 + rr) * 128 + t] = acc[rr];
}

// F4: final edge (uvin) + head + BCE. Warp per node.
__global__ __launch_bounds__(256) void k_dgcn_last(const float* __restrict__ uvin,
                                                   const float* __restrict__ hw,
                                                   const float* __restrict__ hb,
                                                   const int* __restrict__ e0,
                                                   const int* __restrict__ e1,
                                                   const int* __restrict__ e2,
                                                   const int* __restrict__ t0,
                                                   const int* __restrict__ t1,
                                                   const int* __restrict__ t2,
                                                   float* __restrict__ out) {
    int r = blockIdx.x * 8 + (threadIdx.x >> 5);
    int lane = threadIdx.x & 31;
    int b = r / kSN, s = r - b * kSN;
    int rbase, enBase, sc, tgt;
    const int* E;
    if (s < 1024) {
        rbase = b * kSN; sc = 0; tgt = t0[b * 1024 + s];
        E = e0; enBase = b * 16384 + 8192 + s * 8;
    } else if (s < 1792) {
        int q = s - 1024, v = q >> 8, j = q & 255, g = b * 3 + v;
        rbase = b * kSN + 1024 + v * 256; sc = 1; tgt = t1[g * 256 + j];
        E = e1; enBase = g * 4096 + 2048 + j * 8;
    } else {
        int q = s - 1792, v = q >> 6, j = q & 63, g = b * 3 + v;
        rbase = b * kSN + 1792 + v * 64; sc = 2; tgt = t2[g * 64 + j];
        E = e2; enBase = g * 1024 + 512 + j * 8;
    }
    int nv = (lane < 8) ? E[enBase + lane] : 0;
    float u0 = uvin[(size_t)r * 128 + lane];
    float u1 = uvin[(size_t)r * 128 + 32 + lane];
    float m0 = 0.f, m1 = 0.f;
    #pragma unroll
    for (int k = 0; k < 8; k++) {
        int n = rbase + __shfl_sync(0xffffffffu, nv, k);
        m0 = fmaxf(m0, u0 + uvin[(size_t)n * 128 + 64 + lane]);
        m1 = fmaxf(m1, u1 + uvin[(size_t)n * 128 + 96 + lane]);
    }
    float partial = m0 * hw[sc * 64 + lane] + m1 * hw[sc * 64 + 32 + lane];
    partial = warpSum(partial);
    if (lane == 0) {
        float z = partial + hb[sc];
        out[6 + r] = 1.f / (1.f + expf(-z));
        float l = fmaxf(z, 0.f) - z * (float)tgt + log1pf(expf(-fabsf(z)));
        if (tgt > 0) { atomicAdd(&g_bce[sc * 4 + 0], l); atomicAdd(&g_bce[sc * 4 + 2], 1.f); }
        else         { atomicAdd(&g_bce[sc * 4 + 1], l); atomicAdd(&g_bce[sc * 4 + 3], 1.f); }
    }
}

// --------------------------- k11: finalize losses ----------------------------
__global__ void k_final(float* __restrict__ out) {
    int sc = threadIdx.x;
    if (sc < 3) {
        float np = fmaxf(g_bce[sc * 4 + 2], 1.f);
        float nn = fmaxf(g_bce[sc * 4 + 3], 1.f);
        out[sc * 2 + 0] = g_bce[sc * 4 + 0] / np;
        out[sc * 2 + 1] = g_bce[sc * 4 + 1] / nn;
    }
}

// ---------------------------------------------------------------------------
extern "C" void kernel_launch(void* const* d_in, const int* in_sizes, int n_in,
                              void* d_out, int out_size) {
    const float* image      = (const float*)d_in[0];
    const float* bn_gamma   = (const float*)d_in[1];
    const float* bn_beta    = (const float*)d_in[2];
    const int*   ht_idx     = (const int*)  d_in[3];
    const float* ht_w       = (const float*)d_in[4];
    const float* w_htconv   = (const float*)d_in[5];
    const float* htbn_gamma = (const float*)d_in[6];
    const float* htbn_beta  = (const float*)d_in[7];
    const int*   sph_idx    = (const int*)  d_in[8];
    const float* sph_w      = (const float*)d_in[9];
    const float* w_sc       = (const float*)d_in[10];
    const float* b_sc       = (const float*)d_in[11];
    const float* scbn_gamma = (const float*)d_in[12];
    const float* scbn_beta  = (const float*)d_in[13];
    const float* dgcn_w     = (const float*)d_in[14];
    const float* dgcn_b     = (const float*)d_in[15];
    const float* dgcn_hw    = (const float*)d_in[16];
    const float* dgcn_hb    = (const float*)d_in[17];
    const int*   ind0       = (const int*)  d_in[18];
    const int*   ind1       = (const int*)  d_in[19];
    const int*   ind2       = (const int*)  d_in[20];
    const int*   edge0      = (const int*)  d_in[21];
    const int*   edge1      = (const int*)  d_in[22];
    const int*   edge2      = (const int*)  d_in[23];
    const int*   target0    = (const int*)  d_in[24];
    const int*   target1    = (const int*)  d_in[25];
    const int*   target2    = (const int*)  d_in[26];
    float* out = (float*)d_out;

    cudaFuncSetAttribute(k_conv, cudaFuncAttributeMaxDynamicSharedMemorySize,
                         SMEM_CONV);

    k_zero<<<1, 512>>>();
    k_img_stats<<<kC, 256>>>(image);
    k_bnt<<<dim3(kNPIX / 32, kC / 32, kB), dim3(32, 8)>>>(image, bn_gamma, bn_beta);
    k_hough<<<(kB * kNBINS) / 8, 256>>>(ht_idx, ht_w);
    k_wprep<<<(9 * 16384 + 255) / 256, 256>>>(w_htconv);
    k_conv<<<dim3(3, kHTH / 2, kB), 256, SMEM_CONV>>>();
    k_sphere<<<kNR / 8, 256>>>(htbn_gamma, htbn_beta, sph_idx, sph_w,
                               ind0, ind1, ind2);
    k_sconv<<<62, 128>>>(w_sc, b_sc);

    float* uvA; float* uvB;
    cudaGetSymbolAddress((void**)&uvA, g_uv);
    cudaGetSymbolAddress((void**)&uvB, g_uv2);
    k_dgcn_first<<<kNR / 16, 128>>>(dgcn_w, dgcn_b, scbn_gamma, scbn_beta, uvA);
    k_dgcn_mid<<<kNR / 16, 128>>>(dgcn_w, dgcn_b, uvA, uvB, edge0, edge1, edge2, 1);
    k_dgcn_mid<<<kNR / 16, 128>>>(dgcn_w, dgcn_b, uvB, uvA, edge0, edge1, edge2, 2);
    k_dgcn_mid<<<kNR / 16, 128>>>(dgcn_w, dgcn_b, uvA, uvB, edge0, edge1, edge2, 3);
    k_dgcn_last<<<kNR / 8, 256>>>(uvB, dgcn_hw, dgcn_hb, edge0, edge1, edge2,
                                  target0, target1, target2, out);
    k_final<<<1, 32>>>(out);
}

// round 17
// speedup vs baseline: 5.8498x; 1.2542x over previous
#include <cuda_runtime.h>
#include <cuda_fp16.h>
#include <math.h>
#include <stdint.h>

// ---------------------------------------------------------------------------
// VanishingNet full pipeline. R16: fp16 weights single-product conv, fp16
// g_xT / g_ht storage (half traffic on hough + conv A path).
// ---------------------------------------------------------------------------

#define kB     2
#define kC     128
#define kNPIX  16384
#define kHTH   184
#define kHTW   180
#define kNBINS (kHTH * kHTW)   /* 33120 */
#define kSN    1984
#define kNR    (kB * kSN)      /* 3968 */
#define kEPS   1e-5f

// --------------------------- scratch (device globals) ----------------------
__device__ __align__(16) __half g_xT[kB * kNPIX * kC];    // fp16 BN+ReLU image
__device__ __align__(16) __half g_ht[kB * kNBINS * kC];   // fp16 Hough map
__device__ float g_hc [kB * kNBINS * kC];                 // conv out fp32
__device__ float g_sph[kNR * kC];
__device__ float g_y  [kNR * 64];
__device__ float g_uv [kNR * 128];
__device__ float g_uv2[kNR * 128];
__device__ float g_simg[2 * kC];
__device__ float g_sht [2 * kC];
__device__ float g_ssc [2 * 192];
__device__ float g_bce [12];
// pre-swizzled fp16 weight chunks: [tap] 32KB, layout [co][ci]
__device__ __align__(16) unsigned char g_wB[9 * 32768];

__device__ __forceinline__ float warpSum(float v) {
    #pragma unroll
    for (int o = 16; o > 0; o >>= 1) v += __shfl_down_sync(0xffffffffu, v, o);
    return v;
}
__device__ __forceinline__ uint32_t smem_u32(const void* p) {
    uint32_t a;
    asm("{ .reg .u64 t; cvta.to.shared.u64 t, %1; cvt.u32.u64 %0, t; }"
        : "=r"(a) : "l"(p));
    return a;
}
__device__ __forceinline__ void ldsm4(uint32_t* r, uint32_t addr) {
    asm volatile("ldmatrix.sync.aligned.m8n8.x4.shared.b16 {%0,%1,%2,%3}, [%4];"
                 : "=r"(r[0]), "=r"(r[1]), "=r"(r[2]), "=r"(r[3]) : "r"(addr));
}
__device__ __forceinline__ void mma16816(float* d, const uint32_t* a,
                                         const uint32_t* b) {
    asm volatile(
        "mma.sync.aligned.m16n8k16.row.col.f32.f16.f16.f32 "
        "{%0,%1,%2,%3}, {%4,%5,%6,%7}, {%8,%9}, {%0,%1,%2,%3};"
        : "+f"(d[0]), "+f"(d[1]), "+f"(d[2]), "+f"(d[3])
        : "r"(a[0]), "r"(a[1]), "r"(a[2]), "r"(a[3]), "r"(b[0]), "r"(b[1]));
}
__device__ __forceinline__ void cpasync16(uint32_t dst, const void* src) {
    asm volatile("cp.async.cg.shared.global [%0], [%1], 16;"
                 :: "r"(dst), "l"(src));
}

// --------------------------- k0: zero accumulators --------------------------
__global__ void k_zero() {
    int t = threadIdx.x;
    if (t < 2 * kC) { g_sht[t] = 0.f; }
    if (t < 384)    { g_ssc[t] = 0.f; }
    if (t < 12)     { g_bce[t] = 0.f; }
}

// --------------------------- k1: image BN stats ------------------------------
__global__ __launch_bounds__(256) void k_img_stats(const float* __restrict__ img) {
    int c = blockIdx.x, t = threadIdx.x;
    float s = 0.f, s2 = 0.f;
    for (int b = 0; b < kB; b++) {
        const float* p = img + (size_t)(b * kC + c) * kNPIX;
        for (int i = t; i < kNPIX; i += 256) { float v = p[i]; s += v; s2 += v * v; }
    }
    __shared__ float rs[8], rs2[8];
    int lane = t & 31, w = t >> 5;
    s = warpSum(s); s2 = warpSum(s2);
    if (lane == 0) { rs[w] = s; rs2[w] = s2; }
    __syncthreads();
    if (t == 0) {
        float a = 0.f, a2 = 0.f;
        #pragma unroll
        for (int i = 0; i < 8; i++) { a += rs[i]; a2 += rs2[i]; }
        g_simg[c] = a; g_simg[kC + c] = a2;
    }
}

// ---------------- k2: BN + ReLU + transpose to pixel-major fp16 --------------
__global__ void k_bnt(const float* __restrict__ img, const float* __restrict__ gam,
                      const float* __restrict__ bet) {
    __shared__ float tile[32][33];
    int p0 = blockIdx.x * 32, c0 = blockIdx.y * 32, b = blockIdx.z;
    int tx = threadIdx.x, ty = threadIdx.y;
    #pragma unroll
    for (int i = 0; i < 4; i++) {
        int c = c0 + ty * 4 + i;
        tile[ty * 4 + i][tx] = img[(size_t)(b * kC + c) * kNPIX + p0 + tx];
    }
    __syncthreads();
    int c = c0 + tx;
    float mean = g_simg[c] * (1.f / 32768.f);
    float var  = g_simg[kC + c] * (1.f / 32768.f) - mean * mean;
    float sc = gam[c] * rsqrtf(var + kEPS);
    float bi = bet[c] - mean * sc;
    #pragma unroll
    for (int i = 0; i < 4; i++) {
        int p = p0 + ty * 4 + i;
        float v = tile[tx][ty * 4 + i];
        g_xT[(size_t)(b * kNPIX + p) * kC + c] = __float2half(fmaxf(sc * v + bi, 0.f));
    }
}

// --------------------------- k3: Hough voting (warp per bin, fp16) -----------
__global__ __launch_bounds__(256) void k_hough(const int* __restrict__ hidx,
                                               const float* __restrict__ hw) {
    int gw = blockIdx.x * 8 + (threadIdx.x >> 5);
    int lane = threadIdx.x & 31;
    int b = gw / kNBINS, bin = gw - b * kNBINS;
    int   iv = 0; float wv = 0.f;
    if (lane < 8) { iv = hidx[bin * 8 + lane]; wv = hw[bin * 8 + lane]; }
    const uint2* xh = (const uint2*)(g_xT + (size_t)b * kNPIX * kC);
    float4 acc = make_float4(0.f, 0.f, 0.f, 0.f);
    #pragma unroll
    for (int k = 0; k < 8; k++) {
        int   ik = __shfl_sync(0xffffffffu, iv, k);
        float wk = __shfl_sync(0xffffffffu, wv, k);
        uint2 v = xh[(size_t)ik * 32 + lane];
        __half2 h0 = *(__half2*)&v.x;
        __half2 h1 = *(__half2*)&v.y;
        acc.x += wk * __low2float(h0);  acc.y += wk * __high2float(h0);
        acc.z += wk * __low2float(h1);  acc.w += wk * __high2float(h1);
    }
    __half2 o0 = __floats2half2_rn(acc.x, acc.y);
    __half2 o1 = __floats2half2_rn(acc.z, acc.w);
    uint2 o;
    o.x = *(uint32_t*)&o0; o.y = *(uint32_t*)&o1;
    ((uint2*)g_ht)[(size_t)(b * kNBINS + bin) * 32 + lane] = o;
}

// ------------- k_wprep: weights -> pre-swizzled fp16 B chunks ----------------
__global__ void k_wprep(const float* __restrict__ W) {
    int i = blockIdx.x * 256 + threadIdx.x;
    if (i >= 9 * 16384) return;
    int tap = i >> 14, rem = i & 16383;
    int ci = rem >> 7, co = rem & 127;
    float w = W[((size_t)tap * 128 + ci) * 128 + co];
    int off = co * 256 + (((ci >> 3) ^ (co & 7)) << 4) + (ci & 7) * 2;
    *(__half*)(g_wB + (size_t)tap * 32768 + off) = __float2half(w);
}

// --------------------------- k4: fp16 mma.sync conv --------------------------
// CTA tile: M=128 px (2y x 64x) x N=128 cout, 8 warps = 4M x 2N, 2 CTAs/SM.
// A patch: direct fp16 gather/swizzle copy of g_ht (66 KB). 9 B chunks (32KB).
#define PATCH_B   67584              /* 264 rows * 256 B */
#define SM_B      PATCH_B
#define SMEM_CONV (PATCH_B + 32768)  /* 100352 */
__global__ __launch_bounds__(256, 2) void k_conv() {
    extern __shared__ __align__(16) char smem[];
    const uint32_t sA = smem_u32(smem);
    const uint32_t sB = sA + SM_B;
    const int t    = threadIdx.x;
    const int wid  = t >> 5;
    const int lane = t & 31;
    const int x0   = blockIdx.x * 64;
    const int y0   = blockIdx.y * 2;
    const int b    = blockIdx.z;
    const int warpM = wid & 3;
    const int warpN = wid >> 2;

    // ---- prefetch B chunk 0 ----
    {
        uint32_t dst = sB + t * 16;
        const char* src = (const char*)g_wB + t * 16;
        #pragma unroll
        for (int i = 0; i < 8; i++) cpasync16(dst + i * 4096, src + i * 4096);
        asm volatile("cp.async.commit_group;");
    }

    // ---- build A patch: pure fp16 gather + swizzle copy ----
    for (int i = t; i < 264 * 16; i += 256) {
        int row = i >> 4, ch = i & 15;
        int yy = row / 66, xx = row - yy * 66;
        int gy = y0 + yy - 1, gx = x0 + xx - 1;
        bool valid = ((unsigned)gy < kHTH) && ((unsigned)gx < kHTW);
        uint4 v = make_uint4(0u, 0u, 0u, 0u);
        if (valid)
            v = *(const uint4*)((const char*)g_ht
                + (size_t)(b * kNBINS + gy * kHTW + gx) * 256 + ch * 16);
        *(uint4*)(smem + row * 256 + ((ch ^ (row & 7)) << 4)) = v;
    }

    float acc[2][8][4];
    #pragma unroll
    for (int mi = 0; mi < 2; mi++)
        #pragma unroll
        for (int nf = 0; nf < 8; nf++)
            #pragma unroll
            for (int j = 0; j < 4; j++) acc[mi][nf][j] = 0.f;

    const int browA  = warpN * 64 + (lane & 7) + ((lane >> 4) << 3);
    const int bxor   = lane & 7;
    const int bchsel = (lane >> 3) & 1;
    const int asel   = lane >> 4;

    __syncthreads();   // A patch visible

    #pragma unroll 1
    for (int tap = 0; tap < 9; tap++) {
        const int kh = tap / 3, kw = tap - kh * 3;
        asm volatile("cp.async.wait_group 0;");
        __syncthreads();   // chunk visible to all warps

        uint32_t rbase2[2]; int rx[2];
        #pragma unroll
        for (int mi = 0; mi < 2; mi++) {
            int m = warpM * 32 + mi * 16 + (lane & 15);
            int row = ((m >> 6) + kh) * 66 + (m & 63) + kw;
            rbase2[mi] = sA + row * 256;
            rx[mi] = row & 7;
        }
        #pragma unroll 1
        for (int s = 0; s < 8; s++) {
            uint32_t ah[2][4];
            #pragma unroll
            for (int mi = 0; mi < 2; mi++) {
                uint32_t ad = rbase2[mi] + ((((s << 1) + asel) ^ rx[mi]) << 4);
                ldsm4(ah[mi], ad);
            }
            #pragma unroll
            for (int np = 0; np < 4; np++) {
                uint32_t bd = sB + (browA + np * 16) * 256
                            + ((((s << 1) + bchsel) ^ bxor) << 4);
                uint32_t bh[4];
                ldsm4(bh, bd);
                #pragma unroll
                for (int mi = 0; mi < 2; mi++) {
                    mma16816(acc[mi][np * 2],     ah[mi], bh);
                    mma16816(acc[mi][np * 2 + 1], ah[mi], bh + 2);
                }
            }
        }
        __syncthreads();   // compute done before overwrite
        if (tap < 8) {
            uint32_t dst = sB + t * 16;
            const char* src = (const char*)g_wB + (size_t)(tap + 1) * 32768 + t * 16;
            #pragma unroll
            for (int i = 0; i < 8; i++) cpasync16(dst + i * 4096, src + i * 4096);
            asm volatile("cp.async.commit_group;");
        }
    }

    // ---- epilogue: store + fused ht-BN stats ----
    float ls1[16], ls2[16];
    #pragma unroll
    for (int i = 0; i < 16; i++) { ls1[i] = 0.f; ls2[i] = 0.f; }
    #pragma unroll
    for (int mi = 0; mi < 2; mi++) {
        #pragma unroll
        for (int nf = 0; nf < 8; nf++) {
            int n = warpN * 64 + nf * 8 + (lane & 3) * 2;
            int m = warpM * 32 + mi * 16 + (lane >> 2);
            #pragma unroll
            for (int hh = 0; hh < 2; hh++) {
                int px = m + hh * 8;
                int gx = x0 + (px & 63);
                int gy = y0 + (px >> 6);
                if (gx < kHTW) {
                    float v0 = acc[mi][nf][hh * 2];
                    float v1 = acc[mi][nf][hh * 2 + 1];
                    *(float2*)(&g_hc[(size_t)(b * kNBINS + gy * kHTW + gx) * kC + n])
                        = make_float2(v0, v1);
                    ls1[nf * 2]     += v0; ls2[nf * 2]     += v0 * v0;
                    ls1[nf * 2 + 1] += v1; ls2[nf * 2 + 1] += v1 * v1;
                }
            }
        }
    }
    __syncthreads();
    float* sS = (float*)smem;   // reuse A region: 2 x 128ch x 32 contributors
    int contrib = warpM * 8 + (lane >> 2);
    #pragma unroll
    for (int nf = 0; nf < 8; nf++) {
        #pragma unroll
        for (int cb = 0; cb < 2; cb++) {
            int ch = warpN * 64 + nf * 8 + (lane & 3) * 2 + cb;
            sS[ch * 32 + contrib]        = ls1[nf * 2 + cb];
            sS[4096 + ch * 32 + contrib] = ls2[nf * 2 + cb];
        }
    }
    __syncthreads();
    if (t < 128) {
        float a = 0.f, a2 = 0.f;
        #pragma unroll 8
        for (int i = 0; i < 32; i++) {
            a  += sS[t * 32 + i];
            a2 += sS[4096 + t * 32 + i];
        }
        atomicAdd(&g_sht[t], a);
        atomicAdd(&g_sht[kC + t], a2);
    }
}

// ---------------- k6: sphere gather (warp per node, fused ht BN+ReLU) --------
__global__ __launch_bounds__(256) void k_sphere(const float* __restrict__ gam,
                                                const float* __restrict__ bet,
                                                const int* __restrict__ sph_idx,
                                                const float* __restrict__ sph_w,
                                                const int* __restrict__ ind0,
                                                const int* __restrict__ ind1,
                                                const int* __restrict__ ind2) {
    int gw = blockIdx.x * 8 + (threadIdx.x >> 5);
    int lane = threadIdx.x & 31;
    int b = gw / kSN, s = gw - b * kSN;
    int sp;
    if (s < 1024)      sp = ind0[b * 1024 + s];
    else if (s < 1792) sp = ind1[b * 768 + (s - 1024)];
    else               sp = ind2[b * 192 + (s - 1792)];
    int   iv = 0; float wv = 0.f;
    if (lane < 16) { iv = sph_idx[sp * 16 + lane]; wv = sph_w[sp * 16 + lane]; }
    const float inv = 1.f / (float)(kB * kNBINS);
    float4 s1 = ((const float4*)g_sht)[lane];
    float4 s2 = ((const float4*)g_sht)[32 + lane];
    float4 g4 = ((const float4*)gam)[lane];
    float4 b4 = ((const float4*)bet)[lane];
    float4 sc4, bi4;
    {
        float m, v;
        m = s1.x * inv; v = s2.x * inv - m * m; sc4.x = g4.x * rsqrtf(v + kEPS); bi4.x = b4.x - m * sc4.x;
        m = s1.y * inv; v = s2.y * inv - m * m; sc4.y = g4.y * rsqrtf(v + kEPS); bi4.y = b4.y - m * sc4.y;
        m = s1.z * inv; v = s2.z * inv - m * m; sc4.z = g4.z * rsqrtf(v + kEPS); bi4.z = b4.z - m * sc4.z;
        m = s1.w * inv; v = s2.w * inv - m * m; sc4.w = g4.w * rsqrtf(v + kEPS); bi4.w = b4.w - m * sc4.w;
    }
    const float4* base = (const float4*)(g_hc + (size_t)b * kNBINS * kC);
    float4 acc = make_float4(0.f, 0.f, 0.f, 0.f);
    #pragma unroll
    for (int k = 0; k < 16; k++) {
        int   ik = __shfl_sync(0xffffffffu, iv, k);
        float wk = __shfl_sync(0xffffffffu, wv, k);
        float4 v = base[(size_t)ik * 32 + lane];
        acc.x += wk * fmaxf(sc4.x * v.x + bi4.x, 0.f);
        acc.y += wk * fmaxf(sc4.y * v.y + bi4.y, 0.f);
        acc.z += wk * fmaxf(sc4.z * v.z + bi4.z, 0.f);
        acc.w += wk * fmaxf(sc4.w * v.w + bi4.w, 0.f);
    }
    ((float4*)g_sph)[(size_t)(b * kSN + s) * 32 + lane] = acc;
}

// --------------------------- k7: sconv (1x1 conv) + stats --------------------
__global__ __launch_bounds__(128) void k_sconv(const float* __restrict__ w_sc,
                                               const float* __restrict__ b_sc) {
    __shared__ float sWt[128 * 64];
    __shared__ float sRow[2][128];
    int bx = blockIdx.x;
    int b = bx / 31, u = bx % 31;
    int sc, rbase;
    if (u < 16)      { sc = 0; rbase = b * kSN + u * 64; }
    else if (u < 28) { sc = 1; rbase = b * kSN + 1024 + (u - 16) * 64; }
    else             { sc = 2; rbase = b * kSN + 1792 + (u - 28) * 64; }
    int t = threadIdx.x, o = t & 63, half = t >> 6;
    for (int i = t; i < 8192; i += 128) {
        int c = i >> 6, oo = i & 63;
        sWt[i] = w_sc[(size_t)(sc * 64 + oo) * 128 + c];
    }
    __syncthreads();
    float bo = b_sc[sc * 64 + o];
    float ls = 0.f, ls2 = 0.f;
    for (int r0 = 0; r0 < 64; r0 += 2) {
        __syncthreads();
        sRow[0][t] = g_sph[(size_t)(rbase + r0) * 128 + t];
        sRow[1][t] = g_sph[(size_t)(rbase + r0 + 1) * 128 + t];
        __syncthreads();
        const float* rp = sRow[half];
        float acc = bo;
        #pragma unroll 8
        for (int c = 0; c < 128; c++) acc += rp[c] * sWt[c * 64 + o];
        g_y[(size_t)(rbase + r0 + half) * 64 + o] = acc;
        ls += acc; ls2 += acc * acc;
    }
    atomicAdd(&g_ssc[sc * 64 + o], ls);
    atomicAdd(&g_ssc[192 + sc * 64 + o], ls2);
}

// ---------------- dgcn fused kernels ----------------------------------------
__global__ __launch_bounds__(128) void k_dgcn_first(const float* __restrict__ dgw,
                                                    const float* __restrict__ dgb,
                                                    const float* __restrict__ gam,
                                                    const float* __restrict__ bet,
                                                    float* __restrict__ uvout) {
    __shared__ __align__(16) float sWc[64 * 128];
    __shared__ __align__(16) float sX[16 * 64];
    int t = threadIdx.x;
    int r0 = blockIdx.x * 16;
    int b = r0 / kSN, s0 = r0 - b * kSN;
    int sc = (s0 < 1024) ? 0 : (s0 < 1792 ? 1 : 2);
    const float* W  = dgw + (size_t)(sc * 4) * 8192;
    const float* bi = dgb + (size_t)(sc * 4) * 64;
    for (int i = t; i < 4096; i += 128) {
        int c = i >> 6, o = i & 63;
        float w2 = W[4096 + i];
        sWc[c * 128 + o]      = W[i] - w2;
        sWc[c * 128 + 64 + o] = w2;
    }
    {
        int o = t & 63;
        float cnt = (sc == 0) ? 2048.f : (sc == 1 ? 1536.f : 384.f);
        float mean = g_ssc[sc * 64 + o] / cnt;
        float var  = g_ssc[192 + sc * 64 + o] / cnt - mean * mean;
        float scv = gam[sc * 64 + o] * rsqrtf(var + kEPS);
        float biv = bet[sc * 64 + o] - mean * scv;
        for (int i = t; i < 1024; i += 128)
            sX[i] = fmaxf(scv * g_y[(size_t)r0 * 64 + i] + biv, 0.f);
    }
    __syncthreads();
    float acc[16];
    float binit = (t < 64) ? bi[t] : 0.f;
    #pragma unroll
    for (int rr = 0; rr < 16; rr++) acc[rr] = binit;
    #pragma unroll 4
    for (int c4 = 0; c4 < 16; c4++) {
        float w0 = sWc[(c4 * 4 + 0) * 128 + t];
        float w1 = sWc[(c4 * 4 + 1) * 128 + t];
        float w2 = sWc[(c4 * 4 + 2) * 128 + t];
        float w3 = sWc[(c4 * 4 + 3) * 128 + t];
        #pragma unroll
        for (int rr = 0; rr < 16; rr++) {
            float4 xv = *reinterpret_cast<const float4*>(&sX[rr * 64 + c4 * 4]);
            acc[rr] += xv.x * w0 + xv.y * w1 + xv.z * w2 + xv.w * w3;
        }
    }
    #pragma unroll
    for (int rr = 0; rr < 16; rr++)
        uvout[(size_t)(r0 + rr) * 128 + t] = acc[rr];
}

__global__ __launch_bounds__(128) void k_dgcn_mid(const float* __restrict__ dgw,
                                                  const float* __restrict__ dgb,
                                                  const float* __restrict__ uvin,
                                                  float* __restrict__ uvout,
                                                  const int* __restrict__ e0,
                                                  const int* __restrict__ e1,
                                                  const int* __restrict__ e2,
                                                  int layer) {
    __shared__ __align__(16) float sWc[64 * 128];
    __shared__ __align__(16) float sX[16 * 64];
    __shared__ int sNbr[128];
    int t = threadIdx.x;
    int r0 = blockIdx.x * 16;
    int b = r0 / kSN, s0 = r0 - b * kSN;
    int sc = (s0 < 1024) ? 0 : (s0 < 1792 ? 1 : 2);
    const float* W  = dgw + (size_t)(sc * 4 + layer) * 8192;
    const float* bi = dgb + (size_t)(sc * 4 + layer) * 64;
    for (int i = t; i < 4096; i += 128) {
        int c = i >> 6, o = i & 63;
        float w2 = W[4096 + i];
        sWc[c * 128 + o]      = W[i] - w2;
        sWc[c * 128 + 64 + o] = w2;
    }
    {
        int r = r0 + (t >> 3);
        int bb = r / kSN, ss = r - bb * kSN;
        const int* E; int en;
        if (ss < 1024)      { E = e0; en = bb * 16384 + 8192 + ss * 8; }
        else if (ss < 1792) { int q = ss - 1024, v = q >> 8, jj = q & 255, g = bb * 3 + v;
                              E = e1; en = g * 4096 + 2048 + jj * 8; }
        else                { int q = ss - 1792, v = q >> 6, jj = q & 63, g = bb * 3 + v;
                              E = e2; en = g * 1024 + 512 + jj * 8; }
        sNbr[t] = E[en + (t & 7)];
    }
    int rbase;
    if (s0 < 1024)      rbase = b * kSN;
    else if (s0 < 1792) rbase = b * kSN + 1024 + ((s0 - 1024) >> 8) * 256;
    else                rbase = b * kSN + 1792 + ((s0 - 1792) >> 6) * 64;
    __syncthreads();
    {
        int o = t & 63, rg = t >> 6;
        #pragma unroll
        for (int rr8 = 0; rr8 < 8; rr8++) {
            int rr = rg * 8 + rr8;
            float U = uvin[(size_t)(r0 + rr) * 128 + o];
            float m = 0.f;
            #pragma unroll
            for (int k = 0; k < 8; k++) {
                int n = sNbr[rr * 8 + k];
                m = fmaxf(m, U + uvin[(size_t)(rbase + n) * 128 + 64 + o]);
            }
            sX[rr * 64 + o] = m;
        }
    }
    __syncthreads();
    float acc[16];
    float binit = (t < 64) ? bi[t] : 0.f;
    #pragma unroll
    for (int rr = 0; rr < 16; rr++) acc[rr] = binit;
    #pragma unroll 4
    for (int c4 = 0; c4 < 16; c4++) {
        float w0 = sWc[(c4 * 4 + 0) * 128 + t];
        float w1 = sWc[(c4 * 4 + 1) * 128 + t];
        float w2 = sWc[(c4 * 4 + 2) * 128 + t];
        float w3 = sWc[(c4 * 4 + 3) * 128 + t];
        #pragma unroll
        for (int rr = 0; rr < 16; rr++) {
            float4 xv = *reinterpret_cast<const float4*>(&sX[rr * 64 + c4 * 4]);
            acc[rr] += xv.x * w0 + xv.y * w1 + xv.z * w2 + xv.w * w3;
        }
    }
    #pragma unroll
    for (int rr = 0; rr < 16; rr++)
        uvout[(size_t)(r0 + rr) * 128 + t] = acc[rr];
}

__global__ __launch_bounds__(256) void k_dgcn_last(const float* __restrict__ uvin,
                                                   const float* __restrict__ hw,
                                                   const float* __restrict__ hb,
                                                   const int* __restrict__ e0,
                                                   const int* __restrict__ e1,
                                                   const int* __restrict__ e2,
                                                   const int* __restrict__ t0,
                                                   const int* __restrict__ t1,
                                                   const int* __restrict__ t2,
                                                   float* __restrict__ out) {
    int r = blockIdx.x * 8 + (threadIdx.x >> 5);
    int lane = threadIdx.x & 31;
    int b = r / kSN, s = r - b * kSN;
    int rbase, enBase, sc, tgt;
    const int* E;
    if (s < 1024) {
        rbase = b * kSN; sc = 0; tgt = t0[b * 1024 + s];
        E = e0; enBase = b * 16384 + 8192 + s * 8;
    } else if (s < 1792) {
        int q = s - 1024, v = q >> 8, j = q & 255, g = b * 3 + v;
        rbase = b * kSN + 1024 + v * 256; sc = 1; tgt = t1[g * 256 + j];
        E = e1; enBase = g * 4096 + 2048 + j * 8;
    } else {
        int q = s - 1792, v = q >> 6, j = q & 63, g = b * 3 + v;
        rbase = b * kSN + 1792 + v * 64; sc = 2; tgt = t2[g * 64 + j];
        E = e2; enBase = g * 1024 + 512 + j * 8;
    }
    int nv = (lane < 8) ? E[enBase + lane] : 0;
    float u0 = uvin[(size_t)r * 128 + lane];
    float u1 = uvin[(size_t)r * 128 + 32 + lane];
    float m0 = 0.f, m1 = 0.f;
    #pragma unroll
    for (int k = 0; k < 8; k++) {
        int n = rbase + __shfl_sync(0xffffffffu, nv, k);
        m0 = fmaxf(m0, u0 + uvin[(size_t)n * 128 + 64 + lane]);
        m1 = fmaxf(m1, u1 + uvin[(size_t)n * 128 + 96 + lane]);
    }
    float partial = m0 * hw[sc * 64 + lane] + m1 * hw[sc * 64 + 32 + lane];
    partial = warpSum(partial);
    if (lane == 0) {
        float z = partial + hb[sc];
        out[6 + r] = 1.f / (1.f + expf(-z));
        float l = fmaxf(z, 0.f) - z * (float)tgt + log1pf(expf(-fabsf(z)));
        if (tgt > 0) { atomicAdd(&g_bce[sc * 4 + 0], l); atomicAdd(&g_bce[sc * 4 + 2], 1.f); }
        else         { atomicAdd(&g_bce[sc * 4 + 1], l); atomicAdd(&g_bce[sc * 4 + 3], 1.f); }
    }
}

// --------------------------- k11: finalize losses ----------------------------
__global__ void k_final(float* __restrict__ out) {
    int sc = threadIdx.x;
    if (sc < 3) {
        float np = fmaxf(g_bce[sc * 4 + 2], 1.f);
        float nn = fmaxf(g_bce[sc * 4 + 3], 1.f);
        out[sc * 2 + 0] = g_bce[sc * 4 + 0] / np;
        out[sc * 2 + 1] = g_bce[sc * 4 + 1] / nn;
    }
}

// ---------------------------------------------------------------------------
extern "C" void kernel_launch(void* const* d_in, const int* in_sizes, int n_in,
                              void* d_out, int out_size) {
    const float* image      = (const float*)d_in[0];
    const float* bn_gamma   = (const float*)d_in[1];
    const float* bn_beta    = (const float*)d_in[2];
    const int*   ht_idx     = (const int*)  d_in[3];
    const float* ht_w       = (const float*)d_in[4];
    const float* w_htconv   = (const float*)d_in[5];
    const float* htbn_gamma = (const float*)d_in[6];
    const float* htbn_beta  = (const float*)d_in[7];
    const int*   sph_idx    = (const int*)  d_in[8];
    const float* sph_w      = (const float*)d_in[9];
    const float* w_sc       = (const float*)d_in[10];
    const float* b_sc       = (const float*)d_in[11];
    const float* scbn_gamma = (const float*)d_in[12];
    const float* scbn_beta  = (const float*)d_in[13];
    const float* dgcn_w     = (const float*)d_in[14];
    const float* dgcn_b     = (const float*)d_in[15];
    const float* dgcn_hw    = (const float*)d_in[16];
    const float* dgcn_hb    = (const float*)d_in[17];
    const int*   ind0       = (const int*)  d_in[18];
    const int*   ind1       = (const int*)  d_in[19];
    const int*   ind2       = (const int*)  d_in[20];
    const int*   edge0      = (const int*)  d_in[21];
    const int*   edge1      = (const int*)  d_in[22];
    const int*   edge2      = (const int*)  d_in[23];
    const int*   target0    = (const int*)  d_in[24];
    const int*   target1    = (const int*)  d_in[25];
    const int*   target2    = (const int*)  d_in[26];
    float* out = (float*)d_out;

    cudaFuncSetAttribute(k_conv, cudaFuncAttributeMaxDynamicSharedMemorySize,
                         SMEM_CONV);

    k_zero<<<1, 512>>>();
    k_img_stats<<<kC, 256>>>(image);
    k_bnt<<<dim3(kNPIX / 32, kC / 32, kB), dim3(32, 8)>>>(image, bn_gamma, bn_beta);
    k_wprep<<<(9 * 16384 + 255) / 256, 256>>>(w_htconv);
    k_hough<<<(kB * kNBINS) / 8, 256>>>(ht_idx, ht_w);
    k_conv<<<dim3(3, kHTH / 2, kB), 256, SMEM_CONV>>>();
    k_sphere<<<kNR / 8, 256>>>(htbn_gamma, htbn_beta, sph_idx, sph_w,
                               ind0, ind1, ind2);
    k_sconv<<<62, 128>>>(w_sc, b_sc);

    float* uvA; float* uvB;
    cudaGetSymbolAddress((void**)&uvA, g_uv);
    cudaGetSymbolAddress((void**)&uvB, g_uv2);
    k_dgcn_first<<<kNR / 16, 128>>>(dgcn_w, dgcn_b, scbn_gamma, scbn_beta, uvA);
    k_dgcn_mid<<<kNR / 16, 128>>>(dgcn_w, dgcn_b, uvA, uvB, edge0, edge1, edge2, 1);
    k_dgcn_mid<<<kNR / 16, 128>>>(dgcn_w, dgcn_b, uvB, uvA, edge0, edge1, edge2, 2);
    k_dgcn_mid<<<kNR / 16, 128>>>(dgcn_w, dgcn_b, uvA, uvB, edge0, edge1, edge2, 3);
    k_dgcn_last<<<kNR / 8, 256>>>(uvB, dgcn_hw, dgcn_hb, edge0, edge1, edge2,
                                  target0, target1, target2, out);
    k_final<<<1, 32>>>(out);
}